// round 5
// baseline (speedup 1.0000x reference)
#include <cuda_runtime.h>
#include <cuda_bf16.h>
#include <cuda_fp16.h>
#include <cstdint>

#define NN 50000
#define EE 1600000
#define DD 128
#define LN_EPS 1e-5f

// ---------------- scratch (static device globals) ---------------------------
__device__ float g_deg[NN];
__device__ int   g_cnt[NN];
__device__ int   g_rowptr[NN + 1];
__device__ int   g_cursor[NN];
__device__ int2  g_edge[EE];                    // (src, norm bits)
__device__ __half g_xwh[(size_t)NN * DD];       // fp16 GEMM output (gather source)
__device__ float g_hA[(size_t)NN * DD];
__device__ float g_hB[(size_t)NN * DD];
__device__ __nv_bfloat16 g_xhi[(size_t)NN * DD];
__device__ __nv_bfloat16 g_xlo[(size_t)NN * DD];
__device__ __nv_bfloat16 g_Whi[3 * DD * DD];
__device__ __nv_bfloat16 g_Wlo[3 * DD * DD];

__device__ __forceinline__ uint32_t smem_to_u32(const void* p) {
    uint32_t a;
    asm("{ .reg .u64 t; cvta.to.shared.u64 t, %1; cvt.u32.u64 %0, t; }" : "=r"(a) : "l"(p));
    return a;
}

// ---------------- combined conversion + init kernel -------------------------
__global__ __launch_bounds__(256) void k_conv(const float* __restrict__ x,
                                              const float* __restrict__ Ws) {
    int b = blockIdx.x, t = threadIdx.x;
    if (b < 25000) {
        int i = b * 256 + t;
        float v = x[i];
        __nv_bfloat16 hi = __float2bfloat16(v);
        g_xhi[i] = hi;
        g_xlo[i] = __float2bfloat16(v - __bfloat162float(hi));
    } else if (b < 25192) {
        int j = (b - 25000) * 256 + t;     // < 49152
        float v = Ws[j];
        __nv_bfloat16 hi = __float2bfloat16(v);
        g_Whi[j] = hi;
        g_Wlo[j] = __float2bfloat16(v - __bfloat162float(hi));
    } else {
        int i = (b - 25192) * 256 + t;
        if (i < NN) { g_deg[i] = 1.0f; g_cnt[i] = 0; }
    }
}

__global__ void k_degcnt(const int* __restrict__ ei, const float* __restrict__ ew) {
    int e = blockIdx.x * blockDim.x + threadIdx.x;
    if (e < EE) {
        int c = ei[EE + e];
        atomicAdd(&g_deg[c], ew[e]);
        atomicAdd(&g_cnt[c], 1);
    }
}

// single-block scan: 1024 threads x 8 elems/iter, warp-shuffle based
__global__ __launch_bounds__(1024) void k_scan() {
    __shared__ int s_w[32];
    __shared__ int s_carry;
    int tid = threadIdx.x, lane = tid & 31, wid = tid >> 5;
    if (tid == 0) s_carry = 0;
    __syncthreads();
    for (int base = 0; base < NN; base += 8192) {
        int i0 = base + tid * 8;
        int v[8], pref[8], p = 0;
        #pragma unroll
        for (int j = 0; j < 8; j++) {
            int idx = i0 + j;
            v[j] = (idx < NN) ? g_cnt[idx] : 0;
            p += v[j];
            pref[j] = p;
        }
        int t = p;
        #pragma unroll
        for (int off = 1; off < 32; off <<= 1) {
            int u = __shfl_up_sync(0xffffffffu, t, off);
            if (lane >= off) t += u;
        }
        if (lane == 31) s_w[wid] = t;
        __syncthreads();
        if (wid == 0) {
            int w = s_w[lane];
            #pragma unroll
            for (int off = 1; off < 32; off <<= 1) {
                int u = __shfl_up_sync(0xffffffffu, w, off);
                if (lane >= off) w += u;
            }
            s_w[lane] = w;
        }
        __syncthreads();
        int warpExcl = (wid == 0) ? 0 : s_w[wid - 1];
        int carry = s_carry;
        int myBase = carry + warpExcl + (t - p);
        #pragma unroll
        for (int j = 0; j < 8; j++) {
            int idx = i0 + j;
            if (idx < NN) {
                int e = myBase + pref[j] - v[j];
                g_rowptr[idx] = e;
                g_cursor[idx] = e;
            }
        }
        __syncthreads();
        if (tid == 1023) s_carry = carry + s_w[31];
        __syncthreads();
    }
    if (tid == 0) g_rowptr[NN] = EE;
}

__global__ void k_fill(const int* __restrict__ ei, const float* __restrict__ ew) {
    int e = blockIdx.x * blockDim.x + threadIdx.x;
    if (e < EE) {
        int r = ei[e];
        int c = ei[EE + e];
        float nrm = rsqrtf(g_deg[r]) * ew[e] * rsqrtf(g_deg[c]);
        int pos = atomicAdd(&g_cursor[c], 1);
        g_edge[pos] = make_int2(r, __float_as_int(nrm));
    }
}

// ---------------- mma.sync split-bf16 GEMM: outh = fp16(A @ W^T) ------------
#define PADB 136
#define TILE_B (128 * PADB * 2)
#define SMEM_MMA_TOTAL (4 * TILE_B)

__device__ __forceinline__ void ldsm_x4(uint32_t* r, uint32_t addr) {
    asm volatile("ldmatrix.sync.aligned.m8n8.x4.shared.b16 {%0,%1,%2,%3}, [%4];"
                 : "=r"(r[0]), "=r"(r[1]), "=r"(r[2]), "=r"(r[3]) : "r"(addr));
}
__device__ __forceinline__ void mma_bf16(float* c, const uint32_t* a, const uint32_t* b) {
    asm volatile("mma.sync.aligned.m16n8k16.row.col.f32.bf16.bf16.f32 "
                 "{%0,%1,%2,%3}, {%4,%5,%6,%7}, {%8,%9}, {%0,%1,%2,%3};"
                 : "+f"(c[0]), "+f"(c[1]), "+f"(c[2]), "+f"(c[3])
                 : "r"(a[0]), "r"(a[1]), "r"(a[2]), "r"(a[3]), "r"(b[0]), "r"(b[1]));
}

__global__ __launch_bounds__(256) void k_mma(const __nv_bfloat16* __restrict__ Ahi,
                                             const __nv_bfloat16* __restrict__ Alo,
                                             const __nv_bfloat16* __restrict__ Whi,
                                             const __nv_bfloat16* __restrict__ Wlo,
                                             __half* __restrict__ outh) {
    extern __shared__ char smem[];
    uint32_t sbase = smem_to_u32(smem);
    int tid = threadIdx.x;
    int bm = blockIdx.x * 128;

    #pragma unroll
    for (int it = 0; it < 32; it++) {
        int idx = tid + it * 256;
        int tile = idx >> 11;
        int g = idx & 2047;
        int r = g >> 4, c8 = g & 15;
        uint32_t dst = (uint32_t)tile * TILE_B + ((uint32_t)r * PADB + (uint32_t)c8 * 8) * 2;
        uint4 v = make_uint4(0, 0, 0, 0);
        if (tile < 2) {
            int gr = bm + r;
            const __nv_bfloat16* bp = (tile == 0) ? Ahi : Alo;
            if (gr < NN) v = *(const uint4*)(bp + (size_t)gr * 128 + c8 * 8);
        } else {
            const __nv_bfloat16* bp = (tile == 2) ? Whi : Wlo;
            v = *(const uint4*)(bp + r * 128 + c8 * 8);
        }
        *(uint4*)(smem + dst) = v;
    }
    __syncthreads();

    int lane = tid & 31, warp = tid >> 5;
    int wm = warp >> 1, wn = warp & 1;

    uint32_t aoff[2];
    #pragma unroll
    for (int mi = 0; mi < 2; mi++) {
        int row = wm * 32 + mi * 16 + (lane & 15);
        aoff[mi] = ((uint32_t)row * PADB + (uint32_t)(lane >> 4) * 8) * 2;
    }
    uint32_t boff[4];
    #pragma unroll
    for (int pi = 0; pi < 4; pi++) {
        int row = wn * 64 + pi * 16 + (lane & 7) + 8 * ((lane >> 4) & 1);
        boff[pi] = ((uint32_t)row * PADB + (uint32_t)((lane >> 3) & 1) * 8) * 2;
    }

    uint32_t sAhi = sbase + 0 * TILE_B, sAlo = sbase + 1 * TILE_B;
    uint32_t sWhi = sbase + 2 * TILE_B, sWlo = sbase + 3 * TILE_B;

    float C[2][8][4];
    #pragma unroll
    for (int mi = 0; mi < 2; mi++)
        #pragma unroll
        for (int ni = 0; ni < 8; ni++)
            #pragma unroll
            for (int q = 0; q < 4; q++) C[mi][ni][q] = 0.0f;

    #pragma unroll
    for (int ks = 0; ks < 8; ks++) {
        uint32_t kadv = (uint32_t)ks * 32;
        uint32_t ahi[2][4], alo[2][4], bhi[4][4], blo[4][4];
        #pragma unroll
        for (int mi = 0; mi < 2; mi++) {
            ldsm_x4(ahi[mi], sAhi + aoff[mi] + kadv);
            ldsm_x4(alo[mi], sAlo + aoff[mi] + kadv);
        }
        #pragma unroll
        for (int pi = 0; pi < 4; pi++) {
            ldsm_x4(bhi[pi], sWhi + boff[pi] + kadv);
            ldsm_x4(blo[pi], sWlo + boff[pi] + kadv);
        }
        #pragma unroll
        for (int mi = 0; mi < 2; mi++) {
            #pragma unroll
            for (int ni = 0; ni < 8; ni++) {
                const uint32_t* bh = &bhi[ni >> 1][(ni & 1) * 2];
                const uint32_t* bl = &blo[ni >> 1][(ni & 1) * 2];
                mma_bf16(C[mi][ni], ahi[mi], bh);
                mma_bf16(C[mi][ni], ahi[mi], bl);
                mma_bf16(C[mi][ni], alo[mi], bh);
            }
        }
    }

    // epilogue: fp16 stores
    int g = lane >> 2, ctg = lane & 3;
    #pragma unroll
    for (int mi = 0; mi < 2; mi++) {
        int r0 = bm + wm * 32 + mi * 16 + g;
        #pragma unroll
        for (int ni = 0; ni < 8; ni++) {
            int col = wn * 64 + ni * 8 + ctg * 2;
            if (r0 < NN)
                *(__half2*)&outh[(size_t)r0 * 128 + col] =
                    __floats2half2_rn(C[mi][ni][0], C[mi][ni][1]);
            if (r0 + 8 < NN)
                *(__half2*)&outh[(size_t)(r0 + 8) * 128 + col] =
                    __floats2half2_rn(C[mi][ni][2], C[mi][ni][3]);
        }
    }
}

// ---------------- fused aggregate + LN + ReLU + residual (+bf16 conv) -------
// 2 nodes per 128-thread block; 64 threads per node, 2 features each (half2).
__device__ __forceinline__ void slot_bar(int slot) {
    asm volatile("bar.sync %0, 64;" :: "r"(slot + 1) : "memory");
}

__global__ __launch_bounds__(128) void k_agg(const __half* __restrict__ xwh,
                                             const float* __restrict__ hin,
                                             const float* __restrict__ bias,
                                             const float* __restrict__ gamma,
                                             const float* __restrict__ beta,
                                             float* __restrict__ hout,
                                             int flags) {   // bit0 relu, bit1 conv
    int tid = threadIdx.x;
    int slot = tid >> 6, lt = tid & 63;
    int lane = tid & 31, warp = tid >> 5;
    int n = blockIdx.x * 2 + slot;
    int d0 = lt * 2;

    __shared__ int   s_src[2][64];
    __shared__ float s_nrm[2][64];
    __shared__ float s_red[2][4];

    float invdeg = 1.0f / g_deg[n];
    float2 sf = __half22float2(*(const __half2*)&xwh[(size_t)n * DD + d0]);
    float2 bvec = *(const float2*)&bias[d0];
    float ax = invdeg * sf.x + bvec.x;
    float ay = invdeg * sf.y + bvec.y;

    int beg = g_rowptr[n], end = g_rowptr[n + 1];
    for (int c0 = beg; c0 < end; c0 += 64) {
        int m = end - c0;
        if (m > 64) m = 64;
        if (lt < m) {
            int2 e = g_edge[c0 + lt];
            s_src[slot][lt] = e.x;
            s_nrm[slot][lt] = __int_as_float(e.y);
        }
        slot_bar(slot);
        int j = 0;
        int m4 = m & ~3;
        for (; j < m4; j += 4) {
            float w0 = s_nrm[slot][j + 0], w1 = s_nrm[slot][j + 1];
            float w2 = s_nrm[slot][j + 2], w3 = s_nrm[slot][j + 3];
            float2 v0 = __half22float2(*(const __half2*)&xwh[(size_t)s_src[slot][j + 0] * DD + d0]);
            float2 v1 = __half22float2(*(const __half2*)&xwh[(size_t)s_src[slot][j + 1] * DD + d0]);
            float2 v2 = __half22float2(*(const __half2*)&xwh[(size_t)s_src[slot][j + 2] * DD + d0]);
            float2 v3 = __half22float2(*(const __half2*)&xwh[(size_t)s_src[slot][j + 3] * DD + d0]);
            ax += w0 * v0.x; ay += w0 * v0.y;
            ax += w1 * v1.x; ay += w1 * v1.y;
            ax += w2 * v2.x; ay += w2 * v2.y;
            ax += w3 * v3.x; ay += w3 * v3.y;
        }
        for (; j < m; j++) {
            float w = s_nrm[slot][j];
            float2 v = __half22float2(*(const __half2*)&xwh[(size_t)s_src[slot][j] * DD + d0]);
            ax += w * v.x; ay += w * v.y;
        }
        slot_bar(slot);
    }

    // LayerNorm over 128 features (64 threads x 2)
    float s = ax + ay;
    #pragma unroll
    for (int off = 16; off >= 1; off >>= 1) s += __shfl_xor_sync(0xffffffff, s, off);
    if (lane == 0) s_red[0][warp] = s;
    slot_bar(slot);
    float mu = (s_red[0][slot * 2] + s_red[0][slot * 2 + 1]) * (1.0f / 128.0f);

    float dx = ax - mu, dy = ay - mu;
    float q = dx * dx + dy * dy;
    #pragma unroll
    for (int off = 16; off >= 1; off >>= 1) q += __shfl_xor_sync(0xffffffff, q, off);
    if (lane == 0) s_red[1][warp] = q;
    slot_bar(slot);
    float var = (s_red[1][slot * 2] + s_red[1][slot * 2 + 1]) * (1.0f / 128.0f);
    float rstd = rsqrtf(var + LN_EPS);

    float2 gv = *(const float2*)&gamma[d0];
    float2 bt = *(const float2*)&beta[d0];
    float yx = dx * rstd * gv.x + bt.x;
    float yy = dy * rstd * gv.y + bt.y;
    if (flags & 1) { yx = fmaxf(yx, 0.0f); yy = fmaxf(yy, 0.0f); }
    float2 hv = *(const float2*)&hin[(size_t)n * DD + d0];
    yx += hv.x; yy += hv.y;
    *(float2*)&hout[(size_t)n * DD + d0] = make_float2(yx, yy);

    if (flags & 2) {
        size_t i = (size_t)n * DD + d0;
        __nv_bfloat16 hx = __float2bfloat16(yx);
        __nv_bfloat16 hy = __float2bfloat16(yy);
        g_xhi[i] = hx; g_xhi[i + 1] = hy;
        g_xlo[i]     = __float2bfloat16(yx - __bfloat162float(hx));
        g_xlo[i + 1] = __float2bfloat16(yy - __bfloat162float(hy));
    }
}

// ---------------- launch ----------------------------------------------------
extern "C" void kernel_launch(void* const* d_in, const int* in_sizes, int n_in,
                              void* d_out, int out_size) {
    const float* x      = (const float*)d_in[0];
    const int*   ei     = (const int*)  d_in[1];
    const float* ew     = (const float*)d_in[2];
    const float* Ws     = (const float*)d_in[3];
    const float* bs     = (const float*)d_in[4];
    const float* gammas = (const float*)d_in[5];
    const float* betas  = (const float*)d_in[6];
    float* out = (float*)d_out;

    __half* xwh = nullptr; cudaGetSymbolAddress((void**)&xwh, g_xwh);
    float* hA = nullptr; cudaGetSymbolAddress((void**)&hA, g_hA);
    float* hB = nullptr; cudaGetSymbolAddress((void**)&hB, g_hB);
    __nv_bfloat16* xhi = nullptr; cudaGetSymbolAddress((void**)&xhi, g_xhi);
    __nv_bfloat16* xlo = nullptr; cudaGetSymbolAddress((void**)&xlo, g_xlo);
    __nv_bfloat16* Whi = nullptr; cudaGetSymbolAddress((void**)&Whi, g_Whi);
    __nv_bfloat16* Wlo = nullptr; cudaGetSymbolAddress((void**)&Wlo, g_Wlo);

    cudaFuncSetAttribute(k_mma, cudaFuncAttributeMaxDynamicSharedMemorySize, SMEM_MMA_TOTAL);

    int gE = (EE + 255) / 256;
    int gConv = 25192 + (NN + 255) / 256;
    int gMma = (NN + 127) / 128;
    int gAgg = NN / 2;

    k_conv<<<gConv, 256>>>(x, Ws);
    k_degcnt<<<gE, 256>>>(ei, ew);
    k_scan<<<1, 1024>>>();
    k_fill<<<gE, 256>>>(ei, ew);

    k_mma<<<gMma, 256, SMEM_MMA_TOTAL>>>(xhi, xlo, Whi + 0 * DD * DD, Wlo + 0 * DD * DD, xwh);
    k_agg<<<gAgg, 128>>>(xwh, x, bs + 0 * DD, gammas + 0 * DD, betas + 0 * DD, hA, 1 | 2);
    k_mma<<<gMma, 256, SMEM_MMA_TOTAL>>>(xhi, xlo, Whi + 1 * DD * DD, Wlo + 1 * DD * DD, xwh);
    k_agg<<<gAgg, 128>>>(xwh, hA, bs + 1 * DD, gammas + 1 * DD, betas + 1 * DD, hB, 1 | 2);
    k_mma<<<gMma, 256, SMEM_MMA_TOTAL>>>(xhi, xlo, Whi + 2 * DD * DD, Wlo + 2 * DD * DD, xwh);
    k_agg<<<gAgg, 128>>>(xwh, hB, bs + 2 * DD, gammas + 2 * DD, betas + 2 * DD, out, 0);
}

// round 6
// speedup vs baseline: 1.5943x; 1.5943x over previous
#include <cuda_runtime.h>
#include <cuda_bf16.h>
#include <cuda_fp16.h>
#include <cstdint>

#define NN 50000
#define EE 1600000
#define DD 128
#define LN_EPS 1e-5f

// ---------------- scratch (static device globals) ---------------------------
__device__ float g_deg[NN];
__device__ int   g_cnt[NN];
__device__ int   g_rowptr[NN + 1];
__device__ int   g_cursor[NN];
__device__ int2  g_edge[EE];                    // (src, norm bits)
__device__ __half g_xwh[(size_t)NN * DD];       // fp16 GEMM output (gather source)
__device__ float g_hA[(size_t)NN * DD];
__device__ float g_hB[(size_t)NN * DD];
__device__ __nv_bfloat16 g_xhi[(size_t)NN * DD];
__device__ __nv_bfloat16 g_xlo[(size_t)NN * DD];
__device__ __nv_bfloat16 g_Whi[3 * DD * DD];
__device__ __nv_bfloat16 g_Wlo[3 * DD * DD];

__device__ __forceinline__ uint32_t smem_to_u32(const void* p) {
    uint32_t a;
    asm("{ .reg .u64 t; cvta.to.shared.u64 t, %1; cvt.u32.u64 %0, t; }" : "=r"(a) : "l"(p));
    return a;
}

// ---------------- combined conversion + init kernel -------------------------
__global__ __launch_bounds__(256) void k_conv(const float* __restrict__ x,
                                              const float* __restrict__ Ws) {
    int b = blockIdx.x, t = threadIdx.x;
    if (b < 25000) {
        int i = b * 256 + t;
        float v = x[i];
        __nv_bfloat16 hi = __float2bfloat16(v);
        g_xhi[i] = hi;
        g_xlo[i] = __float2bfloat16(v - __bfloat162float(hi));
    } else if (b < 25192) {
        int j = (b - 25000) * 256 + t;     // < 49152
        float v = Ws[j];
        __nv_bfloat16 hi = __float2bfloat16(v);
        g_Whi[j] = hi;
        g_Wlo[j] = __float2bfloat16(v - __bfloat162float(hi));
    } else {
        int i = (b - 25192) * 256 + t;
        if (i < NN) { g_deg[i] = 1.0f; g_cnt[i] = 0; }
    }
}

__global__ void k_degcnt(const int* __restrict__ ei, const float* __restrict__ ew) {
    int e = blockIdx.x * blockDim.x + threadIdx.x;
    if (e < EE) {
        int c = ei[EE + e];
        atomicAdd(&g_deg[c], ew[e]);
        atomicAdd(&g_cnt[c], 1);
    }
}

// single-block scan: 1024 threads x 8 elems/iter, warp-shuffle based
__global__ __launch_bounds__(1024) void k_scan() {
    __shared__ int s_w[32];
    __shared__ int s_carry;
    int tid = threadIdx.x, lane = tid & 31, wid = tid >> 5;
    if (tid == 0) s_carry = 0;
    __syncthreads();
    for (int base = 0; base < NN; base += 8192) {
        int i0 = base + tid * 8;
        int v[8], pref[8], p = 0;
        #pragma unroll
        for (int j = 0; j < 8; j++) {
            int idx = i0 + j;
            v[j] = (idx < NN) ? g_cnt[idx] : 0;
            p += v[j];
            pref[j] = p;
        }
        int t = p;
        #pragma unroll
        for (int off = 1; off < 32; off <<= 1) {
            int u = __shfl_up_sync(0xffffffffu, t, off);
            if (lane >= off) t += u;
        }
        if (lane == 31) s_w[wid] = t;
        __syncthreads();
        if (wid == 0) {
            int w = s_w[lane];
            #pragma unroll
            for (int off = 1; off < 32; off <<= 1) {
                int u = __shfl_up_sync(0xffffffffu, w, off);
                if (lane >= off) w += u;
            }
            s_w[lane] = w;
        }
        __syncthreads();
        int warpExcl = (wid == 0) ? 0 : s_w[wid - 1];
        int carry = s_carry;
        int myBase = carry + warpExcl + (t - p);
        #pragma unroll
        for (int j = 0; j < 8; j++) {
            int idx = i0 + j;
            if (idx < NN) {
                int e = myBase + pref[j] - v[j];
                g_rowptr[idx] = e;
                g_cursor[idx] = e;
            }
        }
        __syncthreads();
        if (tid == 1023) s_carry = carry + s_w[31];
        __syncthreads();
    }
    if (tid == 0) g_rowptr[NN] = EE;
}

__global__ void k_fill(const int* __restrict__ ei, const float* __restrict__ ew) {
    int e = blockIdx.x * blockDim.x + threadIdx.x;
    if (e < EE) {
        int r = ei[e];
        int c = ei[EE + e];
        float nrm = rsqrtf(g_deg[r]) * ew[e] * rsqrtf(g_deg[c]);
        int pos = atomicAdd(&g_cursor[c], 1);
        g_edge[pos] = make_int2(r, __float_as_int(nrm));
    }
}

// ---------------- mma.sync split-bf16 GEMM: outh = fp16(A @ W^T) ------------
#define PADB 136
#define TILE_B (128 * PADB * 2)
#define SMEM_MMA_TOTAL (4 * TILE_B)

__device__ __forceinline__ void ldsm_x4(uint32_t* r, uint32_t addr) {
    asm volatile("ldmatrix.sync.aligned.m8n8.x4.shared.b16 {%0,%1,%2,%3}, [%4];"
                 : "=r"(r[0]), "=r"(r[1]), "=r"(r[2]), "=r"(r[3]) : "r"(addr));
}
__device__ __forceinline__ void mma_bf16(float* c, const uint32_t* a, const uint32_t* b) {
    asm volatile("mma.sync.aligned.m16n8k16.row.col.f32.bf16.bf16.f32 "
                 "{%0,%1,%2,%3}, {%4,%5,%6,%7}, {%8,%9}, {%0,%1,%2,%3};"
                 : "+f"(c[0]), "+f"(c[1]), "+f"(c[2]), "+f"(c[3])
                 : "r"(a[0]), "r"(a[1]), "r"(a[2]), "r"(a[3]), "r"(b[0]), "r"(b[1]));
}

__global__ __launch_bounds__(256) void k_mma(const __nv_bfloat16* __restrict__ Ahi,
                                             const __nv_bfloat16* __restrict__ Alo,
                                             const __nv_bfloat16* __restrict__ Whi,
                                             const __nv_bfloat16* __restrict__ Wlo,
                                             __half* __restrict__ outh) {
    extern __shared__ char smem[];
    uint32_t sbase = smem_to_u32(smem);
    int tid = threadIdx.x;
    int bm = blockIdx.x * 128;

    #pragma unroll
    for (int it = 0; it < 32; it++) {
        int idx = tid + it * 256;
        int tile = idx >> 11;
        int g = idx & 2047;
        int r = g >> 4, c8 = g & 15;
        uint32_t dst = (uint32_t)tile * TILE_B + ((uint32_t)r * PADB + (uint32_t)c8 * 8) * 2;
        uint4 v = make_uint4(0, 0, 0, 0);
        if (tile < 2) {
            int gr = bm + r;
            const __nv_bfloat16* bp = (tile == 0) ? Ahi : Alo;
            if (gr < NN) v = *(const uint4*)(bp + (size_t)gr * 128 + c8 * 8);
        } else {
            const __nv_bfloat16* bp = (tile == 2) ? Whi : Wlo;
            v = *(const uint4*)(bp + r * 128 + c8 * 8);
        }
        *(uint4*)(smem + dst) = v;
    }
    __syncthreads();

    int lane = tid & 31, warp = tid >> 5;
    int wm = warp >> 1, wn = warp & 1;

    uint32_t aoff[2];
    #pragma unroll
    for (int mi = 0; mi < 2; mi++) {
        int row = wm * 32 + mi * 16 + (lane & 15);
        aoff[mi] = ((uint32_t)row * PADB + (uint32_t)(lane >> 4) * 8) * 2;
    }
    uint32_t boff[4];
    #pragma unroll
    for (int pi = 0; pi < 4; pi++) {
        int row = wn * 64 + pi * 16 + (lane & 7) + 8 * ((lane >> 4) & 1);
        boff[pi] = ((uint32_t)row * PADB + (uint32_t)((lane >> 3) & 1) * 8) * 2;
    }

    uint32_t sAhi = sbase + 0 * TILE_B, sAlo = sbase + 1 * TILE_B;
    uint32_t sWhi = sbase + 2 * TILE_B, sWlo = sbase + 3 * TILE_B;

    float C[2][8][4];
    #pragma unroll
    for (int mi = 0; mi < 2; mi++)
        #pragma unroll
        for (int ni = 0; ni < 8; ni++)
            #pragma unroll
            for (int q = 0; q < 4; q++) C[mi][ni][q] = 0.0f;

    #pragma unroll
    for (int ks = 0; ks < 8; ks++) {
        uint32_t kadv = (uint32_t)ks * 32;
        uint32_t ahi[2][4], alo[2][4], bhi[4][4], blo[4][4];
        #pragma unroll
        for (int mi = 0; mi < 2; mi++) {
            ldsm_x4(ahi[mi], sAhi + aoff[mi] + kadv);
            ldsm_x4(alo[mi], sAlo + aoff[mi] + kadv);
        }
        #pragma unroll
        for (int pi = 0; pi < 4; pi++) {
            ldsm_x4(bhi[pi], sWhi + boff[pi] + kadv);
            ldsm_x4(blo[pi], sWlo + boff[pi] + kadv);
        }
        #pragma unroll
        for (int mi = 0; mi < 2; mi++) {
            #pragma unroll
            for (int ni = 0; ni < 8; ni++) {
                const uint32_t* bh = &bhi[ni >> 1][(ni & 1) * 2];
                const uint32_t* bl = &blo[ni >> 1][(ni & 1) * 2];
                mma_bf16(C[mi][ni], ahi[mi], bh);
                mma_bf16(C[mi][ni], ahi[mi], bl);
                mma_bf16(C[mi][ni], alo[mi], bh);
            }
        }
    }

    // epilogue: fp16 stores
    int g = lane >> 2, ctg = lane & 3;
    #pragma unroll
    for (int mi = 0; mi < 2; mi++) {
        int r0 = bm + wm * 32 + mi * 16 + g;
        #pragma unroll
        for (int ni = 0; ni < 8; ni++) {
            int col = wn * 64 + ni * 8 + ctg * 2;
            if (r0 < NN)
                *(__half2*)&outh[(size_t)r0 * 128 + col] =
                    __floats2half2_rn(C[mi][ni][0], C[mi][ni][1]);
            if (r0 + 8 < NN)
                *(__half2*)&outh[(size_t)(r0 + 8) * 128 + col] =
                    __floats2half2_rn(C[mi][ni][2], C[mi][ni][3]);
        }
    }
}

// ---------------- fused aggregate + LN + ReLU + residual (+bf16 conv) -------
// One node per 128-thread block. Threads = 2 edge-lanes x 64 feature-threads.
// sub = tid>>6 processes edges j ≡ sub (mod 2); each thread owns 2 features
// (half2 gather = 128B per warp). Partials merged once at the end.
__global__ __launch_bounds__(128) void k_agg(const __half* __restrict__ xwh,
                                             const float* __restrict__ hin,
                                             const float* __restrict__ bias,
                                             const float* __restrict__ gamma,
                                             const float* __restrict__ beta,
                                             float* __restrict__ hout,
                                             int flags) {   // bit0 relu, bit1 conv
    int tid = threadIdx.x;
    int sub = tid >> 6, lt = tid & 63;
    int d0 = lt * 2;
    int n = blockIdx.x;

    __shared__ int   s_src[128];
    __shared__ float s_nrm[128];
    __shared__ float s_px[64], s_py[64];
    __shared__ float s_red[4];

    float ax = 0.0f, ay = 0.0f;
    if (sub == 0) {
        float invdeg = 1.0f / g_deg[n];
        float2 sf = __half22float2(__ldg((const __half2*)(xwh + (size_t)n * DD + d0)));
        float2 bvec = *(const float2*)&bias[d0];
        ax = invdeg * sf.x + bvec.x;
        ay = invdeg * sf.y + bvec.y;
    }

    int beg = g_rowptr[n], end = g_rowptr[n + 1];
    for (int c0 = beg; c0 < end; c0 += 128) {
        int m = end - c0;
        if (m > 128) m = 128;
        if (tid < m) {
            int2 e = g_edge[c0 + tid];
            s_src[tid] = e.x;
            s_nrm[tid] = __int_as_float(e.y);
        }
        __syncthreads();
        int j = sub;
        for (; j + 6 < m; j += 8) {
            float w0 = s_nrm[j + 0], w1 = s_nrm[j + 2];
            float w2 = s_nrm[j + 4], w3 = s_nrm[j + 6];
            float2 v0 = __half22float2(__ldg((const __half2*)(xwh + (size_t)s_src[j + 0] * DD + d0)));
            float2 v1 = __half22float2(__ldg((const __half2*)(xwh + (size_t)s_src[j + 2] * DD + d0)));
            float2 v2 = __half22float2(__ldg((const __half2*)(xwh + (size_t)s_src[j + 4] * DD + d0)));
            float2 v3 = __half22float2(__ldg((const __half2*)(xwh + (size_t)s_src[j + 6] * DD + d0)));
            ax += w0 * v0.x; ay += w0 * v0.y;
            ax += w1 * v1.x; ay += w1 * v1.y;
            ax += w2 * v2.x; ay += w2 * v2.y;
            ax += w3 * v3.x; ay += w3 * v3.y;
        }
        for (; j < m; j += 2) {
            float w = s_nrm[j];
            float2 v = __half22float2(__ldg((const __half2*)(xwh + (size_t)s_src[j] * DD + d0)));
            ax += w * v.x; ay += w * v.y;
        }
        __syncthreads();
    }

    // merge edge-lane partials: sub1 -> smem, sub0 adds
    if (sub == 1) { s_px[lt] = ax; s_py[lt] = ay; }
    __syncthreads();
    if (sub == 0) { ax += s_px[lt]; ay += s_py[lt]; }

    // LayerNorm on warps 0,1 (threads 0-63); others idle but barrier-uniform
    int lane = tid & 31, warp = tid >> 5;
    float s = ax + ay;
    #pragma unroll
    for (int off = 16; off >= 1; off >>= 1) s += __shfl_xor_sync(0xffffffff, s, off);
    if (lane == 0 && warp < 2) s_red[warp] = s;
    __syncthreads();
    float mu = (s_red[0] + s_red[1]) * (1.0f / 128.0f);

    float dx = ax - mu, dy = ay - mu;
    float q = dx * dx + dy * dy;
    #pragma unroll
    for (int off = 16; off >= 1; off >>= 1) q += __shfl_xor_sync(0xffffffff, q, off);
    if (lane == 0 && warp < 2) s_red[2 + warp] = q;
    __syncthreads();

    if (sub == 0) {
        float var = (s_red[2] + s_red[3]) * (1.0f / 128.0f);
        float rstd = rsqrtf(var + LN_EPS);
        float2 gv = *(const float2*)&gamma[d0];
        float2 bt = *(const float2*)&beta[d0];
        float yx = dx * rstd * gv.x + bt.x;
        float yy = dy * rstd * gv.y + bt.y;
        if (flags & 1) { yx = fmaxf(yx, 0.0f); yy = fmaxf(yy, 0.0f); }
        float2 hv = __ldg((const float2*)&hin[(size_t)n * DD + d0]);
        yx += hv.x; yy += hv.y;
        *(float2*)&hout[(size_t)n * DD + d0] = make_float2(yx, yy);
        if (flags & 2) {
            size_t i = (size_t)n * DD + d0;
            __nv_bfloat16 hx = __float2bfloat16(yx);
            __nv_bfloat16 hy = __float2bfloat16(yy);
            g_xhi[i] = hx; g_xhi[i + 1] = hy;
            g_xlo[i]     = __float2bfloat16(yx - __bfloat162float(hx));
            g_xlo[i + 1] = __float2bfloat16(yy - __bfloat162float(hy));
        }
    }
}

// ---------------- launch ----------------------------------------------------
extern "C" void kernel_launch(void* const* d_in, const int* in_sizes, int n_in,
                              void* d_out, int out_size) {
    const float* x      = (const float*)d_in[0];
    const int*   ei     = (const int*)  d_in[1];
    const float* ew     = (const float*)d_in[2];
    const float* Ws     = (const float*)d_in[3];
    const float* bs     = (const float*)d_in[4];
    const float* gammas = (const float*)d_in[5];
    const float* betas  = (const float*)d_in[6];
    float* out = (float*)d_out;

    __half* xwh = nullptr; cudaGetSymbolAddress((void**)&xwh, g_xwh);
    float* hA = nullptr; cudaGetSymbolAddress((void**)&hA, g_hA);
    float* hB = nullptr; cudaGetSymbolAddress((void**)&hB, g_hB);
    __nv_bfloat16* xhi = nullptr; cudaGetSymbolAddress((void**)&xhi, g_xhi);
    __nv_bfloat16* xlo = nullptr; cudaGetSymbolAddress((void**)&xlo, g_xlo);
    __nv_bfloat16* Whi = nullptr; cudaGetSymbolAddress((void**)&Whi, g_Whi);
    __nv_bfloat16* Wlo = nullptr; cudaGetSymbolAddress((void**)&Wlo, g_Wlo);

    cudaFuncSetAttribute(k_mma, cudaFuncAttributeMaxDynamicSharedMemorySize, SMEM_MMA_TOTAL);

    int gE = (EE + 255) / 256;
    int gConv = 25192 + (NN + 255) / 256;
    int gMma = (NN + 127) / 128;

    k_conv<<<gConv, 256>>>(x, Ws);
    k_degcnt<<<gE, 256>>>(ei, ew);
    k_scan<<<1, 1024>>>();
    k_fill<<<gE, 256>>>(ei, ew);

    k_mma<<<gMma, 256, SMEM_MMA_TOTAL>>>(xhi, xlo, Whi + 0 * DD * DD, Wlo + 0 * DD * DD, xwh);
    k_agg<<<NN, 128>>>(xwh, x, bs + 0 * DD, gammas + 0 * DD, betas + 0 * DD, hA, 1 | 2);
    k_mma<<<gMma, 256, SMEM_MMA_TOTAL>>>(xhi, xlo, Whi + 1 * DD * DD, Wlo + 1 * DD * DD, xwh);
    k_agg<<<NN, 128>>>(xwh, hA, bs + 1 * DD, gammas + 1 * DD, betas + 1 * DD, hB, 1 | 2);
    k_mma<<<gMma, 256, SMEM_MMA_TOTAL>>>(xhi, xlo, Whi + 2 * DD * DD, Wlo + 2 * DD * DD, xwh);
    k_agg<<<NN, 128>>>(xwh, hB, bs + 2 * DD, gammas + 2 * DD, betas + 2 * DD, out, 0);
}

// round 7
// speedup vs baseline: 2.0788x; 1.3039x over previous
#include <cuda_runtime.h>
#include <cuda_bf16.h>
#include <cuda_fp16.h>
#include <cstdint>

#define NN 50000
#define EE 1600000
#define DD 128
#define LN_EPS 1e-5f

// ---------------- scratch (static device globals) ---------------------------
__device__ float g_deg[NN];
__device__ int   g_cnt[NN];
__device__ int   g_rowptr[NN + 1];
__device__ int   g_cursor[NN];
__device__ int2  g_edge[EE];                    // (src, norm bits)
__device__ __half g_xwh[(size_t)NN * DD];       // fp16 GEMM output (gather source)
__device__ float g_hA[(size_t)NN * DD];
__device__ float g_hB[(size_t)NN * DD];
__device__ __nv_bfloat16 g_xhi[(size_t)NN * DD];
__device__ __nv_bfloat16 g_xlo[(size_t)NN * DD];
__device__ __nv_bfloat16 g_Whi[3 * DD * DD];
__device__ __nv_bfloat16 g_Wlo[3 * DD * DD];

__device__ __forceinline__ uint32_t smem_to_u32(const void* p) {
    uint32_t a;
    asm("{ .reg .u64 t; cvta.to.shared.u64 t, %1; cvt.u32.u64 %0, t; }" : "=r"(a) : "l"(p));
    return a;
}

// ---------------- combined conversion + init kernel -------------------------
__global__ __launch_bounds__(256) void k_conv(const float* __restrict__ x,
                                              const float* __restrict__ Ws) {
    int b = blockIdx.x, t = threadIdx.x;
    if (b < 25000) {
        int i = b * 256 + t;
        float v = x[i];
        __nv_bfloat16 hi = __float2bfloat16(v);
        g_xhi[i] = hi;
        g_xlo[i] = __float2bfloat16(v - __bfloat162float(hi));
    } else if (b < 25192) {
        int j = (b - 25000) * 256 + t;     // < 49152
        float v = Ws[j];
        __nv_bfloat16 hi = __float2bfloat16(v);
        g_Whi[j] = hi;
        g_Wlo[j] = __float2bfloat16(v - __bfloat162float(hi));
    } else {
        int i = (b - 25192) * 256 + t;
        if (i < NN) { g_deg[i] = 1.0f; g_cnt[i] = 0; }
    }
}

__global__ void k_degcnt(const int* __restrict__ ei, const float* __restrict__ ew) {
    int e = blockIdx.x * blockDim.x + threadIdx.x;
    if (e < EE) {
        int c = ei[EE + e];
        atomicAdd(&g_deg[c], ew[e]);
        atomicAdd(&g_cnt[c], 1);
    }
}

// single-block scan: 1024 threads x 8 elems/iter, warp-shuffle based
__global__ __launch_bounds__(1024) void k_scan() {
    __shared__ int s_w[32];
    __shared__ int s_carry;
    int tid = threadIdx.x, lane = tid & 31, wid = tid >> 5;
    if (tid == 0) s_carry = 0;
    __syncthreads();
    for (int base = 0; base < NN; base += 8192) {
        int i0 = base + tid * 8;
        int v[8], pref[8], p = 0;
        #pragma unroll
        for (int j = 0; j < 8; j++) {
            int idx = i0 + j;
            v[j] = (idx < NN) ? g_cnt[idx] : 0;
            p += v[j];
            pref[j] = p;
        }
        int t = p;
        #pragma unroll
        for (int off = 1; off < 32; off <<= 1) {
            int u = __shfl_up_sync(0xffffffffu, t, off);
            if (lane >= off) t += u;
        }
        if (lane == 31) s_w[wid] = t;
        __syncthreads();
        if (wid == 0) {
            int w = s_w[lane];
            #pragma unroll
            for (int off = 1; off < 32; off <<= 1) {
                int u = __shfl_up_sync(0xffffffffu, w, off);
                if (lane >= off) w += u;
            }
            s_w[lane] = w;
        }
        __syncthreads();
        int warpExcl = (wid == 0) ? 0 : s_w[wid - 1];
        int carry = s_carry;
        int myBase = carry + warpExcl + (t - p);
        #pragma unroll
        for (int j = 0; j < 8; j++) {
            int idx = i0 + j;
            if (idx < NN) {
                int e = myBase + pref[j] - v[j];
                g_rowptr[idx] = e;
                g_cursor[idx] = e;
            }
        }
        __syncthreads();
        if (tid == 1023) s_carry = carry + s_w[31];
        __syncthreads();
    }
    if (tid == 0) g_rowptr[NN] = EE;
}

__global__ void k_fill(const int* __restrict__ ei, const float* __restrict__ ew) {
    int e = blockIdx.x * blockDim.x + threadIdx.x;
    if (e < EE) {
        int r = ei[e];
        int c = ei[EE + e];
        float nrm = rsqrtf(g_deg[r]) * ew[e] * rsqrtf(g_deg[c]);
        int pos = atomicAdd(&g_cursor[c], 1);
        g_edge[pos] = make_int2(r, __float_as_int(nrm));
    }
}

// ---------------- mma.sync split-bf16 GEMM: outh = fp16(A @ W^T) ------------
#define PADB 136
#define TILE_B (128 * PADB * 2)
#define SMEM_MMA_TOTAL (4 * TILE_B)

__device__ __forceinline__ void ldsm_x4(uint32_t* r, uint32_t addr) {
    asm volatile("ldmatrix.sync.aligned.m8n8.x4.shared.b16 {%0,%1,%2,%3}, [%4];"
                 : "=r"(r[0]), "=r"(r[1]), "=r"(r[2]), "=r"(r[3]) : "r"(addr));
}
__device__ __forceinline__ void mma_bf16(float* c, const uint32_t* a, const uint32_t* b) {
    asm volatile("mma.sync.aligned.m16n8k16.row.col.f32.bf16.bf16.f32 "
                 "{%0,%1,%2,%3}, {%4,%5,%6,%7}, {%8,%9}, {%0,%1,%2,%3};"
                 : "+f"(c[0]), "+f"(c[1]), "+f"(c[2]), "+f"(c[3])
                 : "r"(a[0]), "r"(a[1]), "r"(a[2]), "r"(a[3]), "r"(b[0]), "r"(b[1]));
}

__global__ __launch_bounds__(256) void k_mma(const __nv_bfloat16* __restrict__ Ahi,
                                             const __nv_bfloat16* __restrict__ Alo,
                                             const __nv_bfloat16* __restrict__ Whi,
                                             const __nv_bfloat16* __restrict__ Wlo,
                                             __half* __restrict__ outh) {
    extern __shared__ char smem[];
    uint32_t sbase = smem_to_u32(smem);
    int tid = threadIdx.x;
    int bm = blockIdx.x * 128;

    #pragma unroll
    for (int it = 0; it < 32; it++) {
        int idx = tid + it * 256;
        int tile = idx >> 11;
        int g = idx & 2047;
        int r = g >> 4, c8 = g & 15;
        uint32_t dst = (uint32_t)tile * TILE_B + ((uint32_t)r * PADB + (uint32_t)c8 * 8) * 2;
        uint4 v = make_uint4(0, 0, 0, 0);
        if (tile < 2) {
            int gr = bm + r;
            const __nv_bfloat16* bp = (tile == 0) ? Ahi : Alo;
            if (gr < NN) v = *(const uint4*)(bp + (size_t)gr * 128 + c8 * 8);
        } else {
            const __nv_bfloat16* bp = (tile == 2) ? Whi : Wlo;
            v = *(const uint4*)(bp + r * 128 + c8 * 8);
        }
        *(uint4*)(smem + dst) = v;
    }
    __syncthreads();

    int lane = tid & 31, warp = tid >> 5;
    int wm = warp >> 1, wn = warp & 1;

    uint32_t aoff[2];
    #pragma unroll
    for (int mi = 0; mi < 2; mi++) {
        int row = wm * 32 + mi * 16 + (lane & 15);
        aoff[mi] = ((uint32_t)row * PADB + (uint32_t)(lane >> 4) * 8) * 2;
    }
    uint32_t boff[4];
    #pragma unroll
    for (int pi = 0; pi < 4; pi++) {
        int row = wn * 64 + pi * 16 + (lane & 7) + 8 * ((lane >> 4) & 1);
        boff[pi] = ((uint32_t)row * PADB + (uint32_t)((lane >> 3) & 1) * 8) * 2;
    }

    uint32_t sAhi = sbase + 0 * TILE_B, sAlo = sbase + 1 * TILE_B;
    uint32_t sWhi = sbase + 2 * TILE_B, sWlo = sbase + 3 * TILE_B;

    float C[2][8][4];
    #pragma unroll
    for (int mi = 0; mi < 2; mi++)
        #pragma unroll
        for (int ni = 0; ni < 8; ni++)
            #pragma unroll
            for (int q = 0; q < 4; q++) C[mi][ni][q] = 0.0f;

    #pragma unroll
    for (int ks = 0; ks < 8; ks++) {
        uint32_t kadv = (uint32_t)ks * 32;
        uint32_t ahi[2][4], alo[2][4], bhi[4][4], blo[4][4];
        #pragma unroll
        for (int mi = 0; mi < 2; mi++) {
            ldsm_x4(ahi[mi], sAhi + aoff[mi] + kadv);
            ldsm_x4(alo[mi], sAlo + aoff[mi] + kadv);
        }
        #pragma unroll
        for (int pi = 0; pi < 4; pi++) {
            ldsm_x4(bhi[pi], sWhi + boff[pi] + kadv);
            ldsm_x4(blo[pi], sWlo + boff[pi] + kadv);
        }
        #pragma unroll
        for (int mi = 0; mi < 2; mi++) {
            #pragma unroll
            for (int ni = 0; ni < 8; ni++) {
                const uint32_t* bh = &bhi[ni >> 1][(ni & 1) * 2];
                const uint32_t* bl = &blo[ni >> 1][(ni & 1) * 2];
                mma_bf16(C[mi][ni], ahi[mi], bh);
                mma_bf16(C[mi][ni], ahi[mi], bl);
                mma_bf16(C[mi][ni], alo[mi], bh);
            }
        }
    }

    // epilogue: fp16 stores
    int g = lane >> 2, ctg = lane & 3;
    #pragma unroll
    for (int mi = 0; mi < 2; mi++) {
        int r0 = bm + wm * 32 + mi * 16 + g;
        #pragma unroll
        for (int ni = 0; ni < 8; ni++) {
            int col = wn * 64 + ni * 8 + ctg * 2;
            if (r0 < NN)
                *(__half2*)&outh[(size_t)r0 * 128 + col] =
                    __floats2half2_rn(C[mi][ni][0], C[mi][ni][1]);
            if (r0 + 8 < NN)
                *(__half2*)&outh[(size_t)(r0 + 8) * 128 + col] =
                    __floats2half2_rn(C[mi][ni][2], C[mi][ni][3]);
        }
    }
}

// ---------------- warp-per-node aggregate + LN + ReLU + residual ------------
// One warp per node; lane owns 4 features (8B of the fp16 row). Edge metadata
// broadcast via shfl. No smem, no block barriers.
__global__ __launch_bounds__(256) void k_agg(const __half* __restrict__ xwh,
                                             const float* __restrict__ hin,
                                             const float* __restrict__ bias,
                                             const float* __restrict__ gamma,
                                             const float* __restrict__ beta,
                                             float* __restrict__ hout,
                                             int flags) {   // bit0 relu, bit1 conv
    int warp = threadIdx.x >> 5, lane = threadIdx.x & 31;
    int n = blockIdx.x * 8 + warp;     // grid 6250 * 8 = 50000 exact
    int d0 = lane * 4;

    float invdeg = 1.0f / __ldg(&g_deg[n]);
    uint2 sv = __ldg((const uint2*)(xwh + (size_t)n * DD + d0));
    float2 s01 = __half22float2(*(const __half2*)&sv.x);
    float2 s23 = __half22float2(*(const __half2*)&sv.y);
    float4 bv = __ldg((const float4*)&bias[d0]);
    float a0 = invdeg * s01.x + bv.x;
    float a1 = invdeg * s01.y + bv.y;
    float a2 = invdeg * s23.x + bv.z;
    float a3 = invdeg * s23.y + bv.w;

    int beg = __ldg(&g_rowptr[n]), end = __ldg(&g_rowptr[n + 1]);
    for (int c0 = beg; c0 < end; c0 += 32) {
        int m = end - c0;
        if (m > 32) m = 32;
        int2 e = make_int2(0, 0);
        if (lane < m) e = __ldg(&g_edge[c0 + lane]);
        int j = 0;
        for (; j + 3 < m; j += 4) {
            int s0 = __shfl_sync(0xffffffffu, e.x, j);
            int s1 = __shfl_sync(0xffffffffu, e.x, j + 1);
            int s2 = __shfl_sync(0xffffffffu, e.x, j + 2);
            int s3 = __shfl_sync(0xffffffffu, e.x, j + 3);
            float w0 = __int_as_float(__shfl_sync(0xffffffffu, e.y, j));
            float w1 = __int_as_float(__shfl_sync(0xffffffffu, e.y, j + 1));
            float w2 = __int_as_float(__shfl_sync(0xffffffffu, e.y, j + 2));
            float w3 = __int_as_float(__shfl_sync(0xffffffffu, e.y, j + 3));
            uint2 v0 = __ldg((const uint2*)(xwh + (size_t)s0 * DD + d0));
            uint2 v1 = __ldg((const uint2*)(xwh + (size_t)s1 * DD + d0));
            uint2 v2 = __ldg((const uint2*)(xwh + (size_t)s2 * DD + d0));
            uint2 v3 = __ldg((const uint2*)(xwh + (size_t)s3 * DD + d0));
            float2 p0 = __half22float2(*(const __half2*)&v0.x);
            float2 q0 = __half22float2(*(const __half2*)&v0.y);
            a0 += w0 * p0.x; a1 += w0 * p0.y; a2 += w0 * q0.x; a3 += w0 * q0.y;
            float2 p1 = __half22float2(*(const __half2*)&v1.x);
            float2 q1 = __half22float2(*(const __half2*)&v1.y);
            a0 += w1 * p1.x; a1 += w1 * p1.y; a2 += w1 * q1.x; a3 += w1 * q1.y;
            float2 p2 = __half22float2(*(const __half2*)&v2.x);
            float2 q2 = __half22float2(*(const __half2*)&v2.y);
            a0 += w2 * p2.x; a1 += w2 * p2.y; a2 += w2 * q2.x; a3 += w2 * q2.y;
            float2 p3 = __half22float2(*(const __half2*)&v3.x);
            float2 q3 = __half22float2(*(const __half2*)&v3.y);
            a0 += w3 * p3.x; a1 += w3 * p3.y; a2 += w3 * q3.x; a3 += w3 * q3.y;
        }
        for (; j < m; j++) {
            int s = __shfl_sync(0xffffffffu, e.x, j);
            float w = __int_as_float(__shfl_sync(0xffffffffu, e.y, j));
            uint2 v = __ldg((const uint2*)(xwh + (size_t)s * DD + d0));
            float2 p = __half22float2(*(const __half2*)&v.x);
            float2 q = __half22float2(*(const __half2*)&v.y);
            a0 += w * p.x; a1 += w * p.y; a2 += w * q.x; a3 += w * q.y;
        }
    }

    // warp-level LayerNorm over 128 features (4 per lane)
    float s = a0 + a1 + a2 + a3;
    #pragma unroll
    for (int off = 16; off >= 1; off >>= 1) s += __shfl_xor_sync(0xffffffffu, s, off);
    float mu = s * (1.0f / 128.0f);

    float d0f = a0 - mu, d1f = a1 - mu, d2f = a2 - mu, d3f = a3 - mu;
    float q = d0f * d0f + d1f * d1f + d2f * d2f + d3f * d3f;
    #pragma unroll
    for (int off = 16; off >= 1; off >>= 1) q += __shfl_xor_sync(0xffffffffu, q, off);
    float rstd = rsqrtf(q * (1.0f / 128.0f) + LN_EPS);

    float4 gv = __ldg((const float4*)&gamma[d0]);
    float4 bt = __ldg((const float4*)&beta[d0]);
    float y0 = d0f * rstd * gv.x + bt.x;
    float y1 = d1f * rstd * gv.y + bt.y;
    float y2 = d2f * rstd * gv.z + bt.z;
    float y3 = d3f * rstd * gv.w + bt.w;
    if (flags & 1) {
        y0 = fmaxf(y0, 0.0f); y1 = fmaxf(y1, 0.0f);
        y2 = fmaxf(y2, 0.0f); y3 = fmaxf(y3, 0.0f);
    }
    float4 hv = __ldg((const float4*)&hin[(size_t)n * DD + d0]);
    y0 += hv.x; y1 += hv.y; y2 += hv.z; y3 += hv.w;
    *(float4*)&hout[(size_t)n * DD + d0] = make_float4(y0, y1, y2, y3);

    if (flags & 2) {
        size_t i = (size_t)n * DD + d0;
        __nv_bfloat16 h0 = __float2bfloat16(y0);
        __nv_bfloat16 h1 = __float2bfloat16(y1);
        __nv_bfloat16 h2 = __float2bfloat16(y2);
        __nv_bfloat16 h3 = __float2bfloat16(y3);
        __nv_bfloat162 hi01, hi23;
        hi01.x = h0; hi01.y = h1; hi23.x = h2; hi23.y = h3;
        *(uint2*)&g_xhi[i] = make_uint2(*(uint32_t*)&hi01, *(uint32_t*)&hi23);
        __nv_bfloat162 lo01, lo23;
        lo01.x = __float2bfloat16(y0 - __bfloat162float(h0));
        lo01.y = __float2bfloat16(y1 - __bfloat162float(h1));
        lo23.x = __float2bfloat16(y2 - __bfloat162float(h2));
        lo23.y = __float2bfloat16(y3 - __bfloat162float(h3));
        *(uint2*)&g_xlo[i] = make_uint2(*(uint32_t*)&lo01, *(uint32_t*)&lo23);
    }
}

// ---------------- launch ----------------------------------------------------
extern "C" void kernel_launch(void* const* d_in, const int* in_sizes, int n_in,
                              void* d_out, int out_size) {
    const float* x      = (const float*)d_in[0];
    const int*   ei     = (const int*)  d_in[1];
    const float* ew     = (const float*)d_in[2];
    const float* Ws     = (const float*)d_in[3];
    const float* bs     = (const float*)d_in[4];
    const float* gammas = (const float*)d_in[5];
    const float* betas  = (const float*)d_in[6];
    float* out = (float*)d_out;

    __half* xwh = nullptr; cudaGetSymbolAddress((void**)&xwh, g_xwh);
    float* hA = nullptr; cudaGetSymbolAddress((void**)&hA, g_hA);
    float* hB = nullptr; cudaGetSymbolAddress((void**)&hB, g_hB);
    __nv_bfloat16* xhi = nullptr; cudaGetSymbolAddress((void**)&xhi, g_xhi);
    __nv_bfloat16* xlo = nullptr; cudaGetSymbolAddress((void**)&xlo, g_xlo);
    __nv_bfloat16* Whi = nullptr; cudaGetSymbolAddress((void**)&Whi, g_Whi);
    __nv_bfloat16* Wlo = nullptr; cudaGetSymbolAddress((void**)&Wlo, g_Wlo);

    cudaFuncSetAttribute(k_mma, cudaFuncAttributeMaxDynamicSharedMemorySize, SMEM_MMA_TOTAL);

    int gE = (EE + 255) / 256;
    int gConv = 25192 + (NN + 255) / 256;
    int gMma = (NN + 127) / 128;
    int gAgg = NN / 8;                 // 6250 blocks x 8 warps

    k_conv<<<gConv, 256>>>(x, Ws);
    k_degcnt<<<gE, 256>>>(ei, ew);
    k_scan<<<1, 1024>>>();
    k_fill<<<gE, 256>>>(ei, ew);

    k_mma<<<gMma, 256, SMEM_MMA_TOTAL>>>(xhi, xlo, Whi + 0 * DD * DD, Wlo + 0 * DD * DD, xwh);
    k_agg<<<gAgg, 256>>>(xwh, x, bs + 0 * DD, gammas + 0 * DD, betas + 0 * DD, hA, 1 | 2);
    k_mma<<<gMma, 256, SMEM_MMA_TOTAL>>>(xhi, xlo, Whi + 1 * DD * DD, Wlo + 1 * DD * DD, xwh);
    k_agg<<<gAgg, 256>>>(xwh, hA, bs + 1 * DD, gammas + 1 * DD, betas + 1 * DD, hB, 1 | 2);
    k_mma<<<gMma, 256, SMEM_MMA_TOTAL>>>(xhi, xlo, Whi + 2 * DD * DD, Wlo + 2 * DD * DD, xwh);
    k_agg<<<gAgg, 256>>>(xwh, hB, bs + 2 * DD, gammas + 2 * DD, betas + 2 * DD, out, 0);
}

// round 8
// speedup vs baseline: 2.0877x; 1.0043x over previous
#include <cuda_runtime.h>
#include <cuda_bf16.h>
#include <cuda_fp16.h>
#include <cstdint>

#define NN 50000
#define EE 1600000
#define DD 128
#define LN_EPS 1e-5f

// ---------------- scratch (static device globals) ---------------------------
__device__ float g_deg[NN];
__device__ float g_dinv[NN];
__device__ int   g_cnt[NN];
__device__ int   g_rowptr[NN + 1];
__device__ int   g_cursor[NN];
__device__ int2  g_edge[EE];                    // (src, norm bits)
__device__ __half g_xwh[(size_t)NN * DD];       // fp16 GEMM output (gather source)
__device__ float g_hA[(size_t)NN * DD];
__device__ float g_hB[(size_t)NN * DD];
__device__ __nv_bfloat16 g_xhi[(size_t)NN * DD];
__device__ __nv_bfloat16 g_xlo[(size_t)NN * DD];
__device__ __nv_bfloat16 g_Whi[3 * DD * DD];
__device__ __nv_bfloat16 g_Wlo[3 * DD * DD];

__device__ __forceinline__ uint32_t smem_to_u32(const void* p) {
    uint32_t a;
    asm("{ .reg .u64 t; cvta.to.shared.u64 t, %1; cvt.u32.u64 %0, t; }" : "=r"(a) : "l"(p));
    return a;
}

// ---------------- combined conversion + init kernel -------------------------
__global__ __launch_bounds__(256) void k_conv(const float* __restrict__ x,
                                              const float* __restrict__ Ws) {
    int b = blockIdx.x, t = threadIdx.x;
    if (b < 25000) {
        int i = b * 256 + t;
        float v = x[i];
        __nv_bfloat16 hi = __float2bfloat16(v);
        g_xhi[i] = hi;
        g_xlo[i] = __float2bfloat16(v - __bfloat162float(hi));
    } else if (b < 25192) {
        int j = (b - 25000) * 256 + t;     // < 49152
        float v = Ws[j];
        __nv_bfloat16 hi = __float2bfloat16(v);
        g_Whi[j] = hi;
        g_Wlo[j] = __float2bfloat16(v - __bfloat162float(hi));
    } else {
        int i = (b - 25192) * 256 + t;
        if (i < NN) { g_deg[i] = 1.0f; g_cnt[i] = 0; }
    }
}

__global__ void k_degcnt(const int* __restrict__ ei, const float* __restrict__ ew) {
    int e = blockIdx.x * blockDim.x + threadIdx.x;
    if (e < EE) {
        int c = ei[EE + e];
        atomicAdd(&g_deg[c], ew[e]);
        atomicAdd(&g_cnt[c], 1);
    }
}

// dinv = rsqrt(deg) once per node (keeps MUFU out of the per-edge fill loop)
__global__ void k_dinv() {
    int i = blockIdx.x * blockDim.x + threadIdx.x;
    if (i < NN) g_dinv[i] = rsqrtf(g_deg[i]);
}

// single-block scan: 1024 threads x 8 elems/iter, warp-shuffle based
__global__ __launch_bounds__(1024) void k_scan() {
    __shared__ int s_w[32];
    __shared__ int s_carry;
    int tid = threadIdx.x, lane = tid & 31, wid = tid >> 5;
    if (tid == 0) s_carry = 0;
    __syncthreads();
    for (int base = 0; base < NN; base += 8192) {
        int i0 = base + tid * 8;
        int v[8], pref[8], p = 0;
        #pragma unroll
        for (int j = 0; j < 8; j++) {
            int idx = i0 + j;
            v[j] = (idx < NN) ? g_cnt[idx] : 0;
            p += v[j];
            pref[j] = p;
        }
        int t = p;
        #pragma unroll
        for (int off = 1; off < 32; off <<= 1) {
            int u = __shfl_up_sync(0xffffffffu, t, off);
            if (lane >= off) t += u;
        }
        if (lane == 31) s_w[wid] = t;
        __syncthreads();
        if (wid == 0) {
            int w = s_w[lane];
            #pragma unroll
            for (int off = 1; off < 32; off <<= 1) {
                int u = __shfl_up_sync(0xffffffffu, w, off);
                if (lane >= off) w += u;
            }
            s_w[lane] = w;
        }
        __syncthreads();
        int warpExcl = (wid == 0) ? 0 : s_w[wid - 1];
        int carry = s_carry;
        int myBase = carry + warpExcl + (t - p);
        #pragma unroll
        for (int j = 0; j < 8; j++) {
            int idx = i0 + j;
            if (idx < NN) {
                int e = myBase + pref[j] - v[j];
                g_rowptr[idx] = e;
                g_cursor[idx] = e;
            }
        }
        __syncthreads();
        if (tid == 1023) s_carry = carry + s_w[31];
        __syncthreads();
    }
    if (tid == 0) g_rowptr[NN] = EE;
}

__global__ void k_fill(const int* __restrict__ ei, const float* __restrict__ ew) {
    int e = blockIdx.x * blockDim.x + threadIdx.x;
    if (e < EE) {
        int r = ei[e];
        int c = ei[EE + e];
        float nrm = __ldg(&g_dinv[r]) * ew[e] * __ldg(&g_dinv[c]);
        int pos = atomicAdd(&g_cursor[c], 1);
        g_edge[pos] = make_int2(r, __float_as_int(nrm));
    }
}

// ---------------- mma.sync split-bf16 GEMM: outh = fp16(A @ W^T) ------------
#define PADB 136
#define TILE_B (128 * PADB * 2)
#define SMEM_MMA_TOTAL (4 * TILE_B)

__device__ __forceinline__ void ldsm_x4(uint32_t* r, uint32_t addr) {
    asm volatile("ldmatrix.sync.aligned.m8n8.x4.shared.b16 {%0,%1,%2,%3}, [%4];"
                 : "=r"(r[0]), "=r"(r[1]), "=r"(r[2]), "=r"(r[3]) : "r"(addr));
}
__device__ __forceinline__ void mma_bf16(float* c, const uint32_t* a, const uint32_t* b) {
    asm volatile("mma.sync.aligned.m16n8k16.row.col.f32.bf16.bf16.f32 "
                 "{%0,%1,%2,%3}, {%4,%5,%6,%7}, {%8,%9}, {%0,%1,%2,%3};"
                 : "+f"(c[0]), "+f"(c[1]), "+f"(c[2]), "+f"(c[3])
                 : "r"(a[0]), "r"(a[1]), "r"(a[2]), "r"(a[3]), "r"(b[0]), "r"(b[1]));
}

__global__ __launch_bounds__(256) void k_mma(const __nv_bfloat16* __restrict__ Ahi,
                                             const __nv_bfloat16* __restrict__ Alo,
                                             const __nv_bfloat16* __restrict__ Whi,
                                             const __nv_bfloat16* __restrict__ Wlo,
                                             __half* __restrict__ outh) {
    extern __shared__ char smem[];
    uint32_t sbase = smem_to_u32(smem);
    int tid = threadIdx.x;
    int bm = blockIdx.x * 128;

    #pragma unroll
    for (int it = 0; it < 32; it++) {
        int idx = tid + it * 256;
        int tile = idx >> 11;
        int g = idx & 2047;
        int r = g >> 4, c8 = g & 15;
        uint32_t dst = (uint32_t)tile * TILE_B + ((uint32_t)r * PADB + (uint32_t)c8 * 8) * 2;
        uint4 v = make_uint4(0, 0, 0, 0);
        if (tile < 2) {
            int gr = bm + r;
            const __nv_bfloat16* bp = (tile == 0) ? Ahi : Alo;
            if (gr < NN) v = *(const uint4*)(bp + (size_t)gr * 128 + c8 * 8);
        } else {
            const __nv_bfloat16* bp = (tile == 2) ? Whi : Wlo;
            v = *(const uint4*)(bp + r * 128 + c8 * 8);
        }
        *(uint4*)(smem + dst) = v;
    }
    __syncthreads();

    int lane = tid & 31, warp = tid >> 5;
    int wm = warp >> 1, wn = warp & 1;

    uint32_t aoff[2];
    #pragma unroll
    for (int mi = 0; mi < 2; mi++) {
        int row = wm * 32 + mi * 16 + (lane & 15);
        aoff[mi] = ((uint32_t)row * PADB + (uint32_t)(lane >> 4) * 8) * 2;
    }
    uint32_t boff[4];
    #pragma unroll
    for (int pi = 0; pi < 4; pi++) {
        int row = wn * 64 + pi * 16 + (lane & 7) + 8 * ((lane >> 4) & 1);
        boff[pi] = ((uint32_t)row * PADB + (uint32_t)((lane >> 3) & 1) * 8) * 2;
    }

    uint32_t sAhi = sbase + 0 * TILE_B, sAlo = sbase + 1 * TILE_B;
    uint32_t sWhi = sbase + 2 * TILE_B, sWlo = sbase + 3 * TILE_B;

    float C[2][8][4];
    #pragma unroll
    for (int mi = 0; mi < 2; mi++)
        #pragma unroll
        for (int ni = 0; ni < 8; ni++)
            #pragma unroll
            for (int q = 0; q < 4; q++) C[mi][ni][q] = 0.0f;

    #pragma unroll
    for (int ks = 0; ks < 8; ks++) {
        uint32_t kadv = (uint32_t)ks * 32;
        uint32_t ahi[2][4], alo[2][4], bhi[4][4], blo[4][4];
        #pragma unroll
        for (int mi = 0; mi < 2; mi++) {
            ldsm_x4(ahi[mi], sAhi + aoff[mi] + kadv);
            ldsm_x4(alo[mi], sAlo + aoff[mi] + kadv);
        }
        #pragma unroll
        for (int pi = 0; pi < 4; pi++) {
            ldsm_x4(bhi[pi], sWhi + boff[pi] + kadv);
            ldsm_x4(blo[pi], sWlo + boff[pi] + kadv);
        }
        #pragma unroll
        for (int mi = 0; mi < 2; mi++) {
            #pragma unroll
            for (int ni = 0; ni < 8; ni++) {
                const uint32_t* bh = &bhi[ni >> 1][(ni & 1) * 2];
                const uint32_t* bl = &blo[ni >> 1][(ni & 1) * 2];
                mma_bf16(C[mi][ni], ahi[mi], bh);
                mma_bf16(C[mi][ni], ahi[mi], bl);
                mma_bf16(C[mi][ni], alo[mi], bh);
            }
        }
    }

    // epilogue: fp16 stores
    int g = lane >> 2, ctg = lane & 3;
    #pragma unroll
    for (int mi = 0; mi < 2; mi++) {
        int r0 = bm + wm * 32 + mi * 16 + g;
        #pragma unroll
        for (int ni = 0; ni < 8; ni++) {
            int col = wn * 64 + ni * 8 + ctg * 2;
            if (r0 < NN)
                *(__half2*)&outh[(size_t)r0 * 128 + col] =
                    __floats2half2_rn(C[mi][ni][0], C[mi][ni][1]);
            if (r0 + 8 < NN)
                *(__half2*)&outh[(size_t)(r0 + 8) * 128 + col] =
                    __floats2half2_rn(C[mi][ni][2], C[mi][ni][3]);
        }
    }
}

// ---------------- warp-per-node aggregate + LN + ReLU + residual ------------
// One warp per node; lane owns 4 features. Edge metadata read via warp-uniform
// __ldg (broadcast, L1-cached sequential) — no shuffles, no smem, no barriers.
__global__ __launch_bounds__(256) void k_agg(const __half* __restrict__ xwh,
                                             const float* __restrict__ hin,
                                             const float* __restrict__ bias,
                                             const float* __restrict__ gamma,
                                             const float* __restrict__ beta,
                                             float* __restrict__ hout,
                                             int flags) {   // bit0 relu, bit1 conv
    int warp = threadIdx.x >> 5, lane = threadIdx.x & 31;
    int n = blockIdx.x * 8 + warp;     // grid 6250 * 8 = 50000 exact
    int d0 = lane * 4;

    float invdeg = 1.0f / __ldg(&g_deg[n]);
    uint2 sv = __ldg((const uint2*)(xwh + (size_t)n * DD + d0));
    float2 s01 = __half22float2(*(const __half2*)&sv.x);
    float2 s23 = __half22float2(*(const __half2*)&sv.y);
    float4 bv = __ldg((const float4*)&bias[d0]);
    float a0 = invdeg * s01.x + bv.x;
    float a1 = invdeg * s01.y + bv.y;
    float a2 = invdeg * s23.x + bv.z;
    float a3 = invdeg * s23.y + bv.w;

    int beg = __ldg(&g_rowptr[n]), end = __ldg(&g_rowptr[n + 1]);
    int j = beg;
    for (; j + 3 < end; j += 4) {
        int2 e0 = __ldg(&g_edge[j]);
        int2 e1 = __ldg(&g_edge[j + 1]);
        int2 e2 = __ldg(&g_edge[j + 2]);
        int2 e3 = __ldg(&g_edge[j + 3]);
        uint2 v0 = __ldg((const uint2*)(xwh + (size_t)e0.x * DD + d0));
        uint2 v1 = __ldg((const uint2*)(xwh + (size_t)e1.x * DD + d0));
        uint2 v2 = __ldg((const uint2*)(xwh + (size_t)e2.x * DD + d0));
        uint2 v3 = __ldg((const uint2*)(xwh + (size_t)e3.x * DD + d0));
        float w0 = __int_as_float(e0.y), w1 = __int_as_float(e1.y);
        float w2 = __int_as_float(e2.y), w3 = __int_as_float(e3.y);
        float2 p0 = __half22float2(*(const __half2*)&v0.x);
        float2 q0 = __half22float2(*(const __half2*)&v0.y);
        a0 += w0 * p0.x; a1 += w0 * p0.y; a2 += w0 * q0.x; a3 += w0 * q0.y;
        float2 p1 = __half22float2(*(const __half2*)&v1.x);
        float2 q1 = __half22float2(*(const __half2*)&v1.y);
        a0 += w1 * p1.x; a1 += w1 * p1.y; a2 += w1 * q1.x; a3 += w1 * q1.y;
        float2 p2 = __half22float2(*(const __half2*)&v2.x);
        float2 q2 = __half22float2(*(const __half2*)&v2.y);
        a0 += w2 * p2.x; a1 += w2 * p2.y; a2 += w2 * q2.x; a3 += w2 * q2.y;
        float2 p3 = __half22float2(*(const __half2*)&v3.x);
        float2 q3 = __half22float2(*(const __half2*)&v3.y);
        a0 += w3 * p3.x; a1 += w3 * p3.y; a2 += w3 * q3.x; a3 += w3 * q3.y;
    }
    for (; j < end; j++) {
        int2 e = __ldg(&g_edge[j]);
        float w = __int_as_float(e.y);
        uint2 v = __ldg((const uint2*)(xwh + (size_t)e.x * DD + d0));
        float2 p = __half22float2(*(const __half2*)&v.x);
        float2 q = __half22float2(*(const __half2*)&v.y);
        a0 += w * p.x; a1 += w * p.y; a2 += w * q.x; a3 += w * q.y;
    }

    // warp-level LayerNorm over 128 features (4 per lane)
    float s = a0 + a1 + a2 + a3;
    #pragma unroll
    for (int off = 16; off >= 1; off >>= 1) s += __shfl_xor_sync(0xffffffffu, s, off);
    float mu = s * (1.0f / 128.0f);

    float d0f = a0 - mu, d1f = a1 - mu, d2f = a2 - mu, d3f = a3 - mu;
    float q = d0f * d0f + d1f * d1f + d2f * d2f + d3f * d3f;
    #pragma unroll
    for (int off = 16; off >= 1; off >>= 1) q += __shfl_xor_sync(0xffffffffu, q, off);
    float rstd = rsqrtf(q * (1.0f / 128.0f) + LN_EPS);

    float4 gv = __ldg((const float4*)&gamma[d0]);
    float4 bt = __ldg((const float4*)&beta[d0]);
    float y0 = d0f * rstd * gv.x + bt.x;
    float y1 = d1f * rstd * gv.y + bt.y;
    float y2 = d2f * rstd * gv.z + bt.z;
    float y3 = d3f * rstd * gv.w + bt.w;
    if (flags & 1) {
        y0 = fmaxf(y0, 0.0f); y1 = fmaxf(y1, 0.0f);
        y2 = fmaxf(y2, 0.0f); y3 = fmaxf(y3, 0.0f);
    }
    float4 hv = __ldg((const float4*)&hin[(size_t)n * DD + d0]);
    y0 += hv.x; y1 += hv.y; y2 += hv.z; y3 += hv.w;
    *(float4*)&hout[(size_t)n * DD + d0] = make_float4(y0, y1, y2, y3);

    if (flags & 2) {
        size_t i = (size_t)n * DD + d0;
        __nv_bfloat16 h0 = __float2bfloat16(y0);
        __nv_bfloat16 h1 = __float2bfloat16(y1);
        __nv_bfloat16 h2 = __float2bfloat16(y2);
        __nv_bfloat16 h3 = __float2bfloat16(y3);
        __nv_bfloat162 hi01, hi23;
        hi01.x = h0; hi01.y = h1; hi23.x = h2; hi23.y = h3;
        *(uint2*)&g_xhi[i] = make_uint2(*(uint32_t*)&hi01, *(uint32_t*)&hi23);
        __nv_bfloat162 lo01, lo23;
        lo01.x = __float2bfloat16(y0 - __bfloat162float(h0));
        lo01.y = __float2bfloat16(y1 - __bfloat162float(h1));
        lo23.x = __float2bfloat16(y2 - __bfloat162float(h2));
        lo23.y = __float2bfloat16(y3 - __bfloat162float(h3));
        *(uint2*)&g_xlo[i] = make_uint2(*(uint32_t*)&lo01, *(uint32_t*)&lo23);
    }
}

// ---------------- launch ----------------------------------------------------
extern "C" void kernel_launch(void* const* d_in, const int* in_sizes, int n_in,
                              void* d_out, int out_size) {
    const float* x      = (const float*)d_in[0];
    const int*   ei     = (const int*)  d_in[1];
    const float* ew     = (const float*)d_in[2];
    const float* Ws     = (const float*)d_in[3];
    const float* bs     = (const float*)d_in[4];
    const float* gammas = (const float*)d_in[5];
    const float* betas  = (const float*)d_in[6];
    float* out = (float*)d_out;

    __half* xwh = nullptr; cudaGetSymbolAddress((void**)&xwh, g_xwh);
    float* hA = nullptr; cudaGetSymbolAddress((void**)&hA, g_hA);
    float* hB = nullptr; cudaGetSymbolAddress((void**)&hB, g_hB);
    __nv_bfloat16* xhi = nullptr; cudaGetSymbolAddress((void**)&xhi, g_xhi);
    __nv_bfloat16* xlo = nullptr; cudaGetSymbolAddress((void**)&xlo, g_xlo);
    __nv_bfloat16* Whi = nullptr; cudaGetSymbolAddress((void**)&Whi, g_Whi);
    __nv_bfloat16* Wlo = nullptr; cudaGetSymbolAddress((void**)&Wlo, g_Wlo);

    cudaFuncSetAttribute(k_mma, cudaFuncAttributeMaxDynamicSharedMemorySize, SMEM_MMA_TOTAL);

    int gE = (EE + 255) / 256;
    int gN = (NN + 255) / 256;
    int gConv = 25192 + gN;
    int gMma = (NN + 127) / 128;
    int gAgg = NN / 8;

    k_conv<<<gConv, 256>>>(x, Ws);
    k_degcnt<<<gE, 256>>>(ei, ew);
    k_dinv<<<gN, 256>>>();
    k_scan<<<1, 1024>>>();
    k_fill<<<gE, 256>>>(ei, ew);

    k_mma<<<gMma, 256, SMEM_MMA_TOTAL>>>(xhi, xlo, Whi + 0 * DD * DD, Wlo + 0 * DD * DD, xwh);
    k_agg<<<gAgg, 256>>>(xwh, x, bs + 0 * DD, gammas + 0 * DD, betas + 0 * DD, hA, 1 | 2);
    k_mma<<<gMma, 256, SMEM_MMA_TOTAL>>>(xhi, xlo, Whi + 1 * DD * DD, Wlo + 1 * DD * DD, xwh);
    k_agg<<<gAgg, 256>>>(xwh, hA, bs + 1 * DD, gammas + 1 * DD, betas + 1 * DD, hB, 1 | 2);
    k_mma<<<gMma, 256, SMEM_MMA_TOTAL>>>(xhi, xlo, Whi + 2 * DD * DD, Wlo + 2 * DD * DD, xwh);
    k_agg<<<gAgg, 256>>>(xwh, hB, bs + 2 * DD, gammas + 2 * DD, betas + 2 * DD, out, 0);
}

// round 9
// speedup vs baseline: 2.5036x; 1.1992x over previous
#include <cuda_runtime.h>
#include <cuda_bf16.h>
#include <cuda_fp16.h>
#include <cstdint>

#define NN 50000
#define EE 1600000
#define DD 128
#define LN_EPS 1e-5f
#define SCAN_B 49   // ceil(NN / 1024)

// ---------------- scratch (static device globals) ---------------------------
__device__ float g_deg[NN];
__device__ float g_dinv[NN];
__device__ int   g_cnt[NN];
__device__ int   g_rowptr[NN + 1];
__device__ int   g_cursor[NN];
__device__ int   g_bsum[SCAN_B];
__device__ int   g_boff[SCAN_B];
__device__ int2  g_edge[EE];                    // (src, norm bits)
__device__ __half g_xwh[(size_t)NN * DD];       // fp16 GEMM output (gather source)
__device__ float g_hA[(size_t)NN * DD];
__device__ float g_hB[(size_t)NN * DD];
__device__ __nv_bfloat16 g_xhi[(size_t)NN * DD];
__device__ __nv_bfloat16 g_xlo[(size_t)NN * DD];
__device__ __nv_bfloat16 g_Whi[3 * DD * DD];
__device__ __nv_bfloat16 g_Wlo[3 * DD * DD];

__device__ __forceinline__ uint32_t smem_to_u32(const void* p) {
    uint32_t a;
    asm("{ .reg .u64 t; cvta.to.shared.u64 t, %1; cvt.u32.u64 %0, t; }" : "=r"(a) : "l"(p));
    return a;
}

// ---------------- combined conversion + init kernel -------------------------
__global__ __launch_bounds__(256) void k_conv(const float* __restrict__ x,
                                              const float* __restrict__ Ws) {
    int b = blockIdx.x, t = threadIdx.x;
    if (b < 25000) {
        int i = b * 256 + t;
        float v = x[i];
        __nv_bfloat16 hi = __float2bfloat16(v);
        g_xhi[i] = hi;
        g_xlo[i] = __float2bfloat16(v - __bfloat162float(hi));
    } else if (b < 25192) {
        int j = (b - 25000) * 256 + t;     // < 49152
        float v = Ws[j];
        __nv_bfloat16 hi = __float2bfloat16(v);
        g_Whi[j] = hi;
        g_Wlo[j] = __float2bfloat16(v - __bfloat162float(hi));
    } else {
        int i = (b - 25192) * 256 + t;
        if (i < NN) { g_deg[i] = 1.0f; g_cnt[i] = 0; }
    }
}

__global__ void k_degcnt(const int* __restrict__ ei, const float* __restrict__ ew) {
    int e = blockIdx.x * blockDim.x + threadIdx.x;
    if (e < EE) {
        int c = ei[EE + e];
        atomicAdd(&g_deg[c], ew[e]);
        atomicAdd(&g_cnt[c], 1);
    }
}

// ---------------- hierarchical scan: 49 blocks x 1024 ------------------------
__global__ __launch_bounds__(1024) void k_scan1() {
    __shared__ int s_w[32];
    int b = blockIdx.x, t = threadIdx.x, lane = t & 31, wid = t >> 5;
    int i = b * 1024 + t;
    int v = (i < NN) ? g_cnt[i] : 0;
    int incl = v;
    #pragma unroll
    for (int off = 1; off < 32; off <<= 1) {
        int u = __shfl_up_sync(0xffffffffu, incl, off);
        if (lane >= off) incl += u;
    }
    if (lane == 31) s_w[wid] = incl;
    __syncthreads();
    if (wid == 0) {
        int w = s_w[lane];
        #pragma unroll
        for (int off = 1; off < 32; off <<= 1) {
            int u = __shfl_up_sync(0xffffffffu, w, off);
            if (lane >= off) w += u;
        }
        s_w[lane] = w;
    }
    __syncthreads();
    int base = (wid == 0) ? 0 : s_w[wid - 1];
    if (i < NN) g_rowptr[i] = base + incl - v;     // block-local exclusive
    if (t == 1023) g_bsum[b] = s_w[31];            // block total
}

__global__ void k_scan2() {
    int t = threadIdx.x, lane = t & 31, wid = t >> 5;
    __shared__ int s_tot0;
    int v = (t < SCAN_B) ? g_bsum[t] : 0;
    int incl = v;
    #pragma unroll
    for (int off = 1; off < 32; off <<= 1) {
        int u = __shfl_up_sync(0xffffffffu, incl, off);
        if (lane >= off) incl += u;
    }
    if (t == 31) s_tot0 = incl;
    __syncthreads();
    if (wid == 1) incl += s_tot0;
    if (t < SCAN_B) g_boff[t] = incl - v;          // exclusive block offsets
}

// add block offsets, duplicate to cursor, fused dinv; rowptr[NN]=EE
__global__ __launch_bounds__(1024) void k_scan3() {
    int b = blockIdx.x, t = threadIdx.x;
    int i = b * 1024 + t;
    if (i < NN) {
        int rp = g_rowptr[i] + g_boff[b];
        g_rowptr[i] = rp;
        g_cursor[i] = rp;
        g_dinv[i] = rsqrtf(g_deg[i]);
        if (i == 0) g_rowptr[NN] = EE;
    }
}

__global__ void k_fill(const int* __restrict__ ei, const float* __restrict__ ew) {
    int e = blockIdx.x * blockDim.x + threadIdx.x;
    if (e < EE) {
        int r = ei[e];
        int c = ei[EE + e];
        float nrm = __ldg(&g_dinv[r]) * ew[e] * __ldg(&g_dinv[c]);
        int pos = atomicAdd(&g_cursor[c], 1);
        g_edge[pos] = make_int2(r, __float_as_int(nrm));
    }
}

// ---------------- mma.sync split-bf16 GEMM: outh = fp16(A @ W^T) ------------
#define PADB 136
#define TILE_B (128 * PADB * 2)
#define SMEM_MMA_TOTAL (4 * TILE_B)

__device__ __forceinline__ void ldsm_x4(uint32_t* r, uint32_t addr) {
    asm volatile("ldmatrix.sync.aligned.m8n8.x4.shared.b16 {%0,%1,%2,%3}, [%4];"
                 : "=r"(r[0]), "=r"(r[1]), "=r"(r[2]), "=r"(r[3]) : "r"(addr));
}
__device__ __forceinline__ void mma_bf16(float* c, const uint32_t* a, const uint32_t* b) {
    asm volatile("mma.sync.aligned.m16n8k16.row.col.f32.bf16.bf16.f32 "
                 "{%0,%1,%2,%3}, {%4,%5,%6,%7}, {%8,%9}, {%0,%1,%2,%3};"
                 : "+f"(c[0]), "+f"(c[1]), "+f"(c[2]), "+f"(c[3])
                 : "r"(a[0]), "r"(a[1]), "r"(a[2]), "r"(a[3]), "r"(b[0]), "r"(b[1]));
}

__global__ __launch_bounds__(256) void k_mma(const __nv_bfloat16* __restrict__ Ahi,
                                             const __nv_bfloat16* __restrict__ Alo,
                                             const __nv_bfloat16* __restrict__ Whi,
                                             const __nv_bfloat16* __restrict__ Wlo,
                                             __half* __restrict__ outh) {
    extern __shared__ char smem[];
    uint32_t sbase = smem_to_u32(smem);
    int tid = threadIdx.x;
    int bm = blockIdx.x * 128;

    #pragma unroll
    for (int it = 0; it < 32; it++) {
        int idx = tid + it * 256;
        int tile = idx >> 11;
        int g = idx & 2047;
        int r = g >> 4, c8 = g & 15;
        uint32_t dst = (uint32_t)tile * TILE_B + ((uint32_t)r * PADB + (uint32_t)c8 * 8) * 2;
        uint4 v = make_uint4(0, 0, 0, 0);
        if (tile < 2) {
            int gr = bm + r;
            const __nv_bfloat16* bp = (tile == 0) ? Ahi : Alo;
            if (gr < NN) v = *(const uint4*)(bp + (size_t)gr * 128 + c8 * 8);
        } else {
            const __nv_bfloat16* bp = (tile == 2) ? Whi : Wlo;
            v = *(const uint4*)(bp + r * 128 + c8 * 8);
        }
        *(uint4*)(smem + dst) = v;
    }
    __syncthreads();

    int lane = tid & 31, warp = tid >> 5;
    int wm = warp >> 1, wn = warp & 1;

    uint32_t aoff[2];
    #pragma unroll
    for (int mi = 0; mi < 2; mi++) {
        int row = wm * 32 + mi * 16 + (lane & 15);
        aoff[mi] = ((uint32_t)row * PADB + (uint32_t)(lane >> 4) * 8) * 2;
    }
    uint32_t boff[4];
    #pragma unroll
    for (int pi = 0; pi < 4; pi++) {
        int row = wn * 64 + pi * 16 + (lane & 7) + 8 * ((lane >> 4) & 1);
        boff[pi] = ((uint32_t)row * PADB + (uint32_t)((lane >> 3) & 1) * 8) * 2;
    }

    uint32_t sAhi = sbase + 0 * TILE_B, sAlo = sbase + 1 * TILE_B;
    uint32_t sWhi = sbase + 2 * TILE_B, sWlo = sbase + 3 * TILE_B;

    float C[2][8][4];
    #pragma unroll
    for (int mi = 0; mi < 2; mi++)
        #pragma unroll
        for (int ni = 0; ni < 8; ni++)
            #pragma unroll
            for (int q = 0; q < 4; q++) C[mi][ni][q] = 0.0f;

    #pragma unroll
    for (int ks = 0; ks < 8; ks++) {
        uint32_t kadv = (uint32_t)ks * 32;
        uint32_t ahi[2][4], alo[2][4], bhi[4][4], blo[4][4];
        #pragma unroll
        for (int mi = 0; mi < 2; mi++) {
            ldsm_x4(ahi[mi], sAhi + aoff[mi] + kadv);
            ldsm_x4(alo[mi], sAlo + aoff[mi] + kadv);
        }
        #pragma unroll
        for (int pi = 0; pi < 4; pi++) {
            ldsm_x4(bhi[pi], sWhi + boff[pi] + kadv);
            ldsm_x4(blo[pi], sWlo + boff[pi] + kadv);
        }
        #pragma unroll
        for (int mi = 0; mi < 2; mi++) {
            #pragma unroll
            for (int ni = 0; ni < 8; ni++) {
                const uint32_t* bh = &bhi[ni >> 1][(ni & 1) * 2];
                const uint32_t* bl = &blo[ni >> 1][(ni & 1) * 2];
                mma_bf16(C[mi][ni], ahi[mi], bh);
                mma_bf16(C[mi][ni], ahi[mi], bl);
                mma_bf16(C[mi][ni], alo[mi], bh);
            }
        }
    }

    // epilogue: fp16 stores
    int g = lane >> 2, ctg = lane & 3;
    #pragma unroll
    for (int mi = 0; mi < 2; mi++) {
        int r0 = bm + wm * 32 + mi * 16 + g;
        #pragma unroll
        for (int ni = 0; ni < 8; ni++) {
            int col = wn * 64 + ni * 8 + ctg * 2;
            if (r0 < NN)
                *(__half2*)&outh[(size_t)r0 * 128 + col] =
                    __floats2half2_rn(C[mi][ni][0], C[mi][ni][1]);
            if (r0 + 8 < NN)
                *(__half2*)&outh[(size_t)(r0 + 8) * 128 + col] =
                    __floats2half2_rn(C[mi][ni][2], C[mi][ni][3]);
        }
    }
}

// ---------------- warp-per-node aggregate + LN + ReLU + residual ------------
__global__ __launch_bounds__(256) void k_agg(const __half* __restrict__ xwh,
                                             const float* __restrict__ hin,
                                             const float* __restrict__ bias,
                                             const float* __restrict__ gamma,
                                             const float* __restrict__ beta,
                                             float* __restrict__ hout,
                                             int flags) {   // bit0 relu, bit1 conv
    int warp = threadIdx.x >> 5, lane = threadIdx.x & 31;
    int n = blockIdx.x * 8 + warp;     // grid 6250 * 8 = 50000 exact
    int d0 = lane * 4;

    float invdeg = 1.0f / __ldg(&g_deg[n]);
    uint2 sv = __ldg((const uint2*)(xwh + (size_t)n * DD + d0));
    float2 s01 = __half22float2(*(const __half2*)&sv.x);
    float2 s23 = __half22float2(*(const __half2*)&sv.y);
    float4 bv = __ldg((const float4*)&bias[d0]);
    float a0 = invdeg * s01.x + bv.x;
    float a1 = invdeg * s01.y + bv.y;
    float a2 = invdeg * s23.x + bv.z;
    float a3 = invdeg * s23.y + bv.w;

    int beg = __ldg(&g_rowptr[n]), end = __ldg(&g_rowptr[n + 1]);
    int j = beg;
    for (; j + 3 < end; j += 4) {
        int2 e0 = __ldg(&g_edge[j]);
        int2 e1 = __ldg(&g_edge[j + 1]);
        int2 e2 = __ldg(&g_edge[j + 2]);
        int2 e3 = __ldg(&g_edge[j + 3]);
        uint2 v0 = __ldg((const uint2*)(xwh + (size_t)e0.x * DD + d0));
        uint2 v1 = __ldg((const uint2*)(xwh + (size_t)e1.x * DD + d0));
        uint2 v2 = __ldg((const uint2*)(xwh + (size_t)e2.x * DD + d0));
        uint2 v3 = __ldg((const uint2*)(xwh + (size_t)e3.x * DD + d0));
        float w0 = __int_as_float(e0.y), w1 = __int_as_float(e1.y);
        float w2 = __int_as_float(e2.y), w3 = __int_as_float(e3.y);
        float2 p0 = __half22float2(*(const __half2*)&v0.x);
        float2 q0 = __half22float2(*(const __half2*)&v0.y);
        a0 += w0 * p0.x; a1 += w0 * p0.y; a2 += w0 * q0.x; a3 += w0 * q0.y;
        float2 p1 = __half22float2(*(const __half2*)&v1.x);
        float2 q1 = __half22float2(*(const __half2*)&v1.y);
        a0 += w1 * p1.x; a1 += w1 * p1.y; a2 += w1 * q1.x; a3 += w1 * q1.y;
        float2 p2 = __half22float2(*(const __half2*)&v2.x);
        float2 q2 = __half22float2(*(const __half2*)&v2.y);
        a0 += w2 * p2.x; a1 += w2 * p2.y; a2 += w2 * q2.x; a3 += w2 * q2.y;
        float2 p3 = __half22float2(*(const __half2*)&v3.x);
        float2 q3 = __half22float2(*(const __half2*)&v3.y);
        a0 += w3 * p3.x; a1 += w3 * p3.y; a2 += w3 * q3.x; a3 += w3 * q3.y;
    }
    for (; j < end; j++) {
        int2 e = __ldg(&g_edge[j]);
        float w = __int_as_float(e.y);
        uint2 v = __ldg((const uint2*)(xwh + (size_t)e.x * DD + d0));
        float2 p = __half22float2(*(const __half2*)&v.x);
        float2 q = __half22float2(*(const __half2*)&v.y);
        a0 += w * p.x; a1 += w * p.y; a2 += w * q.x; a3 += w * q.y;
    }

    // warp-level LayerNorm over 128 features (4 per lane)
    float s = a0 + a1 + a2 + a3;
    #pragma unroll
    for (int off = 16; off >= 1; off >>= 1) s += __shfl_xor_sync(0xffffffffu, s, off);
    float mu = s * (1.0f / 128.0f);

    float d0f = a0 - mu, d1f = a1 - mu, d2f = a2 - mu, d3f = a3 - mu;
    float q = d0f * d0f + d1f * d1f + d2f * d2f + d3f * d3f;
    #pragma unroll
    for (int off = 16; off >= 1; off >>= 1) q += __shfl_xor_sync(0xffffffffu, q, off);
    float rstd = rsqrtf(q * (1.0f / 128.0f) + LN_EPS);

    float4 gv = __ldg((const float4*)&gamma[d0]);
    float4 bt = __ldg((const float4*)&beta[d0]);
    float y0 = d0f * rstd * gv.x + bt.x;
    float y1 = d1f * rstd * gv.y + bt.y;
    float y2 = d2f * rstd * gv.z + bt.z;
    float y3 = d3f * rstd * gv.w + bt.w;
    if (flags & 1) {
        y0 = fmaxf(y0, 0.0f); y1 = fmaxf(y1, 0.0f);
        y2 = fmaxf(y2, 0.0f); y3 = fmaxf(y3, 0.0f);
    }
    float4 hv = __ldg((const float4*)&hin[(size_t)n * DD + d0]);
    y0 += hv.x; y1 += hv.y; y2 += hv.z; y3 += hv.w;
    *(float4*)&hout[(size_t)n * DD + d0] = make_float4(y0, y1, y2, y3);

    if (flags & 2) {
        size_t i = (size_t)n * DD + d0;
        __nv_bfloat16 h0 = __float2bfloat16(y0);
        __nv_bfloat16 h1 = __float2bfloat16(y1);
        __nv_bfloat16 h2 = __float2bfloat16(y2);
        __nv_bfloat16 h3 = __float2bfloat16(y3);
        __nv_bfloat162 hi01, hi23;
        hi01.x = h0; hi01.y = h1; hi23.x = h2; hi23.y = h3;
        *(uint2*)&g_xhi[i] = make_uint2(*(uint32_t*)&hi01, *(uint32_t*)&hi23);
        __nv_bfloat162 lo01, lo23;
        lo01.x = __float2bfloat16(y0 - __bfloat162float(h0));
        lo01.y = __float2bfloat16(y1 - __bfloat162float(h1));
        lo23.x = __float2bfloat16(y2 - __bfloat162float(h2));
        lo23.y = __float2bfloat16(y3 - __bfloat162float(h3));
        *(uint2*)&g_xlo[i] = make_uint2(*(uint32_t*)&lo01, *(uint32_t*)&lo23);
    }
}

// ---------------- launch ----------------------------------------------------
extern "C" void kernel_launch(void* const* d_in, const int* in_sizes, int n_in,
                              void* d_out, int out_size) {
    const float* x      = (const float*)d_in[0];
    const int*   ei     = (const int*)  d_in[1];
    const float* ew     = (const float*)d_in[2];
    const float* Ws     = (const float*)d_in[3];
    const float* bs     = (const float*)d_in[4];
    const float* gammas = (const float*)d_in[5];
    const float* betas  = (const float*)d_in[6];
    float* out = (float*)d_out;

    __half* xwh = nullptr; cudaGetSymbolAddress((void**)&xwh, g_xwh);
    float* hA = nullptr; cudaGetSymbolAddress((void**)&hA, g_hA);
    float* hB = nullptr; cudaGetSymbolAddress((void**)&hB, g_hB);
    __nv_bfloat16* xhi = nullptr; cudaGetSymbolAddress((void**)&xhi, g_xhi);
    __nv_bfloat16* xlo = nullptr; cudaGetSymbolAddress((void**)&xlo, g_xlo);
    __nv_bfloat16* Whi = nullptr; cudaGetSymbolAddress((void**)&Whi, g_Whi);
    __nv_bfloat16* Wlo = nullptr; cudaGetSymbolAddress((void**)&Wlo, g_Wlo);

    cudaFuncSetAttribute(k_mma, cudaFuncAttributeMaxDynamicSharedMemorySize, SMEM_MMA_TOTAL);

    int gE = (EE + 255) / 256;
    int gConv = 25192 + (NN + 255) / 256;
    int gMma = (NN + 127) / 128;
    int gAgg = NN / 8;

    k_conv<<<gConv, 256>>>(x, Ws);
    k_degcnt<<<gE, 256>>>(ei, ew);
    k_scan1<<<SCAN_B, 1024>>>();
    k_scan2<<<1, 64>>>();
    k_scan3<<<SCAN_B, 1024>>>();
    k_fill<<<gE, 256>>>(ei, ew);

    k_mma<<<gMma, 256, SMEM_MMA_TOTAL>>>(xhi, xlo, Whi + 0 * DD * DD, Wlo + 0 * DD * DD, xwh);
    k_agg<<<gAgg, 256>>>(xwh, x, bs + 0 * DD, gammas + 0 * DD, betas + 0 * DD, hA, 1 | 2);
    k_mma<<<gMma, 256, SMEM_MMA_TOTAL>>>(xhi, xlo, Whi + 1 * DD * DD, Wlo + 1 * DD * DD, xwh);
    k_agg<<<gAgg, 256>>>(xwh, hA, bs + 1 * DD, gammas + 1 * DD, betas + 1 * DD, hB, 1 | 2);
    k_mma<<<gMma, 256, SMEM_MMA_TOTAL>>>(xhi, xlo, Whi + 2 * DD * DD, Wlo + 2 * DD * DD, xwh);
    k_agg<<<gAgg, 256>>>(xwh, hB, bs + 2 * DD, gammas + 2 * DD, betas + 2 * DD, out, 0);
}

// round 10
// speedup vs baseline: 2.7023x; 1.0794x over previous
#include <cuda_runtime.h>
#include <cuda_bf16.h>
#include <cuda_fp16.h>
#include <cstdint>

#define NN 50000
#define EE 1600000
#define DD 128
#define LN_EPS 1e-5f
#define SCAN_B 49   // ceil(NN / 1024)

// ---------------- scratch (static device globals) ---------------------------
__device__ float g_deg[NN];
__device__ float g_dinv[NN];
__device__ int   g_cnt[NN];
__device__ int   g_rowptr[NN + 1];
__device__ int   g_cursor[NN];
__device__ int   g_bsum[SCAN_B];
__device__ int2  g_edge[EE];                    // (src, norm bits)
__device__ __half g_xwh[(size_t)NN * DD];       // fp16 GEMM output (gather source)
__device__ float g_hA[(size_t)NN * DD];
__device__ float g_hB[(size_t)NN * DD];
__device__ __nv_bfloat16 g_xhi[(size_t)NN * DD];
__device__ __nv_bfloat16 g_xlo[(size_t)NN * DD];
__device__ __nv_bfloat16 g_Whi[3 * DD * DD];
__device__ __nv_bfloat16 g_Wlo[3 * DD * DD];

__device__ __forceinline__ uint32_t smem_to_u32(const void* p) {
    uint32_t a;
    asm("{ .reg .u64 t; cvta.to.shared.u64 t, %1; cvt.u32.u64 %0, t; }" : "=r"(a) : "l"(p));
    return a;
}

// ---------------- init (must precede degcnt atomics) -------------------------
__global__ void k_init() {
    int i = blockIdx.x * blockDim.x + threadIdx.x;
    if (i < NN) { g_deg[i] = 1.0f; g_cnt[i] = 0; }
}

// ---------------- merged conversion + degree/count kernel --------------------
// blocks [0,25000): x -> hi/lo ; [25000,25192): W -> hi/lo ; rest: degcnt
__global__ __launch_bounds__(256) void k_main(const float* __restrict__ x,
                                              const float* __restrict__ Ws,
                                              const int* __restrict__ ei,
                                              const float* __restrict__ ew) {
    int b = blockIdx.x, t = threadIdx.x;
    if (b < 25000) {
        int i = b * 256 + t;
        float v = x[i];
        __nv_bfloat16 hi = __float2bfloat16(v);
        g_xhi[i] = hi;
        g_xlo[i] = __float2bfloat16(v - __bfloat162float(hi));
    } else if (b < 25192) {
        int j = (b - 25000) * 256 + t;     // < 49152
        float v = Ws[j];
        __nv_bfloat16 hi = __float2bfloat16(v);
        g_Whi[j] = hi;
        g_Wlo[j] = __float2bfloat16(v - __bfloat162float(hi));
    } else {
        int e = (b - 25192) * 256 + t;
        if (e < EE) {
            int c = ei[EE + e];
            atomicAdd(&g_deg[c], ew[e]);
            atomicAdd(&g_cnt[c], 1);
        }
    }
}

// ---------------- hierarchical scan: 49 blocks x 1024 ------------------------
__global__ __launch_bounds__(1024) void k_scan1() {
    __shared__ int s_w[32];
    int b = blockIdx.x, t = threadIdx.x, lane = t & 31, wid = t >> 5;
    int i = b * 1024 + t;
    int v = (i < NN) ? g_cnt[i] : 0;
    int incl = v;
    #pragma unroll
    for (int off = 1; off < 32; off <<= 1) {
        int u = __shfl_up_sync(0xffffffffu, incl, off);
        if (lane >= off) incl += u;
    }
    if (lane == 31) s_w[wid] = incl;
    __syncthreads();
    if (wid == 0) {
        int w = s_w[lane];
        #pragma unroll
        for (int off = 1; off < 32; off <<= 1) {
            int u = __shfl_up_sync(0xffffffffu, w, off);
            if (lane >= off) w += u;
        }
        s_w[lane] = w;
    }
    __syncthreads();
    int base = (wid == 0) ? 0 : s_w[wid - 1];
    if (i < NN) g_rowptr[i] = base + incl - v;     // block-local exclusive
    if (t == 1023) g_bsum[b] = s_w[31];            // block total
}

// apply block offsets (each block reduces bsum[0..b-1] itself), cursor, dinv
__global__ __launch_bounds__(1024) void k_scan3() {
    __shared__ int s_off;
    int b = blockIdx.x, t = threadIdx.x, lane = t & 31;
    if (t < 32) {
        int acc = 0;
        if (lane < b) acc = g_bsum[lane];                       // lanes 0..b-1 (b<=48 fits... b up to 48)
        if (lane + 32 < b) acc += g_bsum[lane + 32];
        #pragma unroll
        for (int off = 16; off >= 1; off >>= 1) acc += __shfl_xor_sync(0xffffffffu, acc, off);
        if (lane == 0) s_off = acc;
    }
    __syncthreads();
    int i = b * 1024 + t;
    if (i < NN) {
        int rp = g_rowptr[i] + s_off;
        g_rowptr[i] = rp;
        g_cursor[i] = rp;
        g_dinv[i] = rsqrtf(g_deg[i]);
        if (i == 0) g_rowptr[NN] = EE;
    }
}

__global__ void k_fill(const int* __restrict__ ei, const float* __restrict__ ew) {
    int e = blockIdx.x * blockDim.x + threadIdx.x;
    if (e < EE) {
        int r = ei[e];
        int c = ei[EE + e];
        float nrm = __ldg(&g_dinv[r]) * ew[e] * __ldg(&g_dinv[c]);
        int pos = atomicAdd(&g_cursor[c], 1);
        g_edge[pos] = make_int2(r, __float_as_int(nrm));
    }
}

// ---------------- mma.sync split-bf16 GEMM: outh = fp16(A @ W^T) ------------
#define PADB 136
#define TILE_B (128 * PADB * 2)
#define SMEM_MMA_TOTAL (4 * TILE_B)

__device__ __forceinline__ void ldsm_x4(uint32_t* r, uint32_t addr) {
    asm volatile("ldmatrix.sync.aligned.m8n8.x4.shared.b16 {%0,%1,%2,%3}, [%4];"
                 : "=r"(r[0]), "=r"(r[1]), "=r"(r[2]), "=r"(r[3]) : "r"(addr));
}
__device__ __forceinline__ void mma_bf16(float* c, const uint32_t* a, const uint32_t* b) {
    asm volatile("mma.sync.aligned.m16n8k16.row.col.f32.bf16.bf16.f32 "
                 "{%0,%1,%2,%3}, {%4,%5,%6,%7}, {%8,%9}, {%0,%1,%2,%3};"
                 : "+f"(c[0]), "+f"(c[1]), "+f"(c[2]), "+f"(c[3])
                 : "r"(a[0]), "r"(a[1]), "r"(a[2]), "r"(a[3]), "r"(b[0]), "r"(b[1]));
}

__global__ __launch_bounds__(256) void k_mma(const __nv_bfloat16* __restrict__ Ahi,
                                             const __nv_bfloat16* __restrict__ Alo,
                                             const __nv_bfloat16* __restrict__ Whi,
                                             const __nv_bfloat16* __restrict__ Wlo,
                                             __half* __restrict__ outh) {
    extern __shared__ char smem[];
    uint32_t sbase = smem_to_u32(smem);
    int tid = threadIdx.x;
    int bm = blockIdx.x * 128;

    #pragma unroll
    for (int it = 0; it < 32; it++) {
        int idx = tid + it * 256;
        int tile = idx >> 11;
        int g = idx & 2047;
        int r = g >> 4, c8 = g & 15;
        uint32_t dst = (uint32_t)tile * TILE_B + ((uint32_t)r * PADB + (uint32_t)c8 * 8) * 2;
        uint4 v = make_uint4(0, 0, 0, 0);
        if (tile < 2) {
            int gr = bm + r;
            const __nv_bfloat16* bp = (tile == 0) ? Ahi : Alo;
            if (gr < NN) v = *(const uint4*)(bp + (size_t)gr * 128 + c8 * 8);
        } else {
            const __nv_bfloat16* bp = (tile == 2) ? Whi : Wlo;
            v = *(const uint4*)(bp + r * 128 + c8 * 8);
        }
        *(uint4*)(smem + dst) = v;
    }
    __syncthreads();

    int lane = tid & 31, warp = tid >> 5;
    int wm = warp >> 1, wn = warp & 1;

    uint32_t aoff[2];
    #pragma unroll
    for (int mi = 0; mi < 2; mi++) {
        int row = wm * 32 + mi * 16 + (lane & 15);
        aoff[mi] = ((uint32_t)row * PADB + (uint32_t)(lane >> 4) * 8) * 2;
    }
    uint32_t boff[4];
    #pragma unroll
    for (int pi = 0; pi < 4; pi++) {
        int row = wn * 64 + pi * 16 + (lane & 7) + 8 * ((lane >> 4) & 1);
        boff[pi] = ((uint32_t)row * PADB + (uint32_t)((lane >> 3) & 1) * 8) * 2;
    }

    uint32_t sAhi = sbase + 0 * TILE_B, sAlo = sbase + 1 * TILE_B;
    uint32_t sWhi = sbase + 2 * TILE_B, sWlo = sbase + 3 * TILE_B;

    float C[2][8][4];
    #pragma unroll
    for (int mi = 0; mi < 2; mi++)
        #pragma unroll
        for (int ni = 0; ni < 8; ni++)
            #pragma unroll
            for (int q = 0; q < 4; q++) C[mi][ni][q] = 0.0f;

    #pragma unroll
    for (int ks = 0; ks < 8; ks++) {
        uint32_t kadv = (uint32_t)ks * 32;
        uint32_t ahi[2][4], alo[2][4], bhi[4][4], blo[4][4];
        #pragma unroll
        for (int mi = 0; mi < 2; mi++) {
            ldsm_x4(ahi[mi], sAhi + aoff[mi] + kadv);
            ldsm_x4(alo[mi], sAlo + aoff[mi] + kadv);
        }
        #pragma unroll
        for (int pi = 0; pi < 4; pi++) {
            ldsm_x4(bhi[pi], sWhi + boff[pi] + kadv);
            ldsm_x4(blo[pi], sWlo + boff[pi] + kadv);
        }
        #pragma unroll
        for (int mi = 0; mi < 2; mi++) {
            #pragma unroll
            for (int ni = 0; ni < 8; ni++) {
                const uint32_t* bh = &bhi[ni >> 1][(ni & 1) * 2];
                const uint32_t* bl = &blo[ni >> 1][(ni & 1) * 2];
                mma_bf16(C[mi][ni], ahi[mi], bh);
                mma_bf16(C[mi][ni], ahi[mi], bl);
                mma_bf16(C[mi][ni], alo[mi], bh);
            }
        }
    }

    // epilogue: fp16 stores
    int g = lane >> 2, ctg = lane & 3;
    #pragma unroll
    for (int mi = 0; mi < 2; mi++) {
        int r0 = bm + wm * 32 + mi * 16 + g;
        #pragma unroll
        for (int ni = 0; ni < 8; ni++) {
            int col = wn * 64 + ni * 8 + ctg * 2;
            if (r0 < NN)
                *(__half2*)&outh[(size_t)r0 * 128 + col] =
                    __floats2half2_rn(C[mi][ni][0], C[mi][ni][1]);
            if (r0 + 8 < NN)
                *(__half2*)&outh[(size_t)(r0 + 8) * 128 + col] =
                    __floats2half2_rn(C[mi][ni][2], C[mi][ni][3]);
        }
    }
}

// ---------------- warp-per-node aggregate + LN + ReLU + residual ------------
__global__ __launch_bounds__(256) void k_agg(const __half* __restrict__ xwh,
                                             const float* __restrict__ hin,
                                             const float* __restrict__ bias,
                                             const float* __restrict__ gamma,
                                             const float* __restrict__ beta,
                                             float* __restrict__ hout,
                                             int flags) {   // bit0 relu, bit1 conv
    int warp = threadIdx.x >> 5, lane = threadIdx.x & 31;
    int n = blockIdx.x * 8 + warp;     // grid 6250 * 8 = 50000 exact
    int d0 = lane * 4;

    float invdeg = 1.0f / __ldg(&g_deg[n]);
    uint2 sv = __ldg((const uint2*)(xwh + (size_t)n * DD + d0));
    float2 s01 = __half22float2(*(const __half2*)&sv.x);
    float2 s23 = __half22float2(*(const __half2*)&sv.y);
    float4 bv = __ldg((const float4*)&bias[d0]);
    float a0 = invdeg * s01.x + bv.x;
    float a1 = invdeg * s01.y + bv.y;
    float a2 = invdeg * s23.x + bv.z;
    float a3 = invdeg * s23.y + bv.w;

    int beg = __ldg(&g_rowptr[n]), end = __ldg(&g_rowptr[n + 1]);
    int j = beg;
    for (; j + 7 < end; j += 8) {
        int2 e0 = __ldg(&g_edge[j]);
        int2 e1 = __ldg(&g_edge[j + 1]);
        int2 e2 = __ldg(&g_edge[j + 2]);
        int2 e3 = __ldg(&g_edge[j + 3]);
        int2 e4 = __ldg(&g_edge[j + 4]);
        int2 e5 = __ldg(&g_edge[j + 5]);
        int2 e6 = __ldg(&g_edge[j + 6]);
        int2 e7 = __ldg(&g_edge[j + 7]);
        uint2 v0 = __ldg((const uint2*)(xwh + (size_t)e0.x * DD + d0));
        uint2 v1 = __ldg((const uint2*)(xwh + (size_t)e1.x * DD + d0));
        uint2 v2 = __ldg((const uint2*)(xwh + (size_t)e2.x * DD + d0));
        uint2 v3 = __ldg((const uint2*)(xwh + (size_t)e3.x * DD + d0));
        uint2 v4 = __ldg((const uint2*)(xwh + (size_t)e4.x * DD + d0));
        uint2 v5 = __ldg((const uint2*)(xwh + (size_t)e5.x * DD + d0));
        uint2 v6 = __ldg((const uint2*)(xwh + (size_t)e6.x * DD + d0));
        uint2 v7 = __ldg((const uint2*)(xwh + (size_t)e7.x * DD + d0));
        float w0 = __int_as_float(e0.y), w1 = __int_as_float(e1.y);
        float w2 = __int_as_float(e2.y), w3 = __int_as_float(e3.y);
        float w4 = __int_as_float(e4.y), w5 = __int_as_float(e5.y);
        float w6 = __int_as_float(e6.y), w7 = __int_as_float(e7.y);
        float2 p, q;
        p = __half22float2(*(const __half2*)&v0.x); q = __half22float2(*(const __half2*)&v0.y);
        a0 += w0 * p.x; a1 += w0 * p.y; a2 += w0 * q.x; a3 += w0 * q.y;
        p = __half22float2(*(const __half2*)&v1.x); q = __half22float2(*(const __half2*)&v1.y);
        a0 += w1 * p.x; a1 += w1 * p.y; a2 += w1 * q.x; a3 += w1 * q.y;
        p = __half22float2(*(const __half2*)&v2.x); q = __half22float2(*(const __half2*)&v2.y);
        a0 += w2 * p.x; a1 += w2 * p.y; a2 += w2 * q.x; a3 += w2 * q.y;
        p = __half22float2(*(const __half2*)&v3.x); q = __half22float2(*(const __half2*)&v3.y);
        a0 += w3 * p.x; a1 += w3 * p.y; a2 += w3 * q.x; a3 += w3 * q.y;
        p = __half22float2(*(const __half2*)&v4.x); q = __half22float2(*(const __half2*)&v4.y);
        a0 += w4 * p.x; a1 += w4 * p.y; a2 += w4 * q.x; a3 += w4 * q.y;
        p = __half22float2(*(const __half2*)&v5.x); q = __half22float2(*(const __half2*)&v5.y);
        a0 += w5 * p.x; a1 += w5 * p.y; a2 += w5 * q.x; a3 += w5 * q.y;
        p = __half22float2(*(const __half2*)&v6.x); q = __half22float2(*(const __half2*)&v6.y);
        a0 += w6 * p.x; a1 += w6 * p.y; a2 += w6 * q.x; a3 += w6 * q.y;
        p = __half22float2(*(const __half2*)&v7.x); q = __half22float2(*(const __half2*)&v7.y);
        a0 += w7 * p.x; a1 += w7 * p.y; a2 += w7 * q.x; a3 += w7 * q.y;
    }
    for (; j < end; j++) {
        int2 e = __ldg(&g_edge[j]);
        float w = __int_as_float(e.y);
        uint2 v = __ldg((const uint2*)(xwh + (size_t)e.x * DD + d0));
        float2 p = __half22float2(*(const __half2*)&v.x);
        float2 q = __half22float2(*(const __half2*)&v.y);
        a0 += w * p.x; a1 += w * p.y; a2 += w * q.x; a3 += w * q.y;
    }

    // warp-level LayerNorm over 128 features (4 per lane)
    float s = a0 + a1 + a2 + a3;
    #pragma unroll
    for (int off = 16; off >= 1; off >>= 1) s += __shfl_xor_sync(0xffffffffu, s, off);
    float mu = s * (1.0f / 128.0f);

    float d0f = a0 - mu, d1f = a1 - mu, d2f = a2 - mu, d3f = a3 - mu;
    float q = d0f * d0f + d1f * d1f + d2f * d2f + d3f * d3f;
    #pragma unroll
    for (int off = 16; off >= 1; off >>= 1) q += __shfl_xor_sync(0xffffffffu, q, off);
    float rstd = rsqrtf(q * (1.0f / 128.0f) + LN_EPS);

    float4 gv = __ldg((const float4*)&gamma[d0]);
    float4 bt = __ldg((const float4*)&beta[d0]);
    float y0 = d0f * rstd * gv.x + bt.x;
    float y1 = d1f * rstd * gv.y + bt.y;
    float y2 = d2f * rstd * gv.z + bt.z;
    float y3 = d3f * rstd * gv.w + bt.w;
    if (flags & 1) {
        y0 = fmaxf(y0, 0.0f); y1 = fmaxf(y1, 0.0f);
        y2 = fmaxf(y2, 0.0f); y3 = fmaxf(y3, 0.0f);
    }
    float4 hv = __ldg((const float4*)&hin[(size_t)n * DD + d0]);
    y0 += hv.x; y1 += hv.y; y2 += hv.z; y3 += hv.w;
    *(float4*)&hout[(size_t)n * DD + d0] = make_float4(y0, y1, y2, y3);

    if (flags & 2) {
        size_t i = (size_t)n * DD + d0;
        __nv_bfloat16 h0 = __float2bfloat16(y0);
        __nv_bfloat16 h1 = __float2bfloat16(y1);
        __nv_bfloat16 h2 = __float2bfloat16(y2);
        __nv_bfloat16 h3 = __float2bfloat16(y3);
        __nv_bfloat162 hi01, hi23;
        hi01.x = h0; hi01.y = h1; hi23.x = h2; hi23.y = h3;
        *(uint2*)&g_xhi[i] = make_uint2(*(uint32_t*)&hi01, *(uint32_t*)&hi23);
        __nv_bfloat162 lo01, lo23;
        lo01.x = __float2bfloat16(y0 - __bfloat162float(h0));
        lo01.y = __float2bfloat16(y1 - __bfloat162float(h1));
        lo23.x = __float2bfloat16(y2 - __bfloat162float(h2));
        lo23.y = __float2bfloat16(y3 - __bfloat162float(h3));
        *(uint2*)&g_xlo[i] = make_uint2(*(uint32_t*)&lo01, *(uint32_t*)&lo23);
    }
}

// ---------------- launch ----------------------------------------------------
extern "C" void kernel_launch(void* const* d_in, const int* in_sizes, int n_in,
                              void* d_out, int out_size) {
    const float* x      = (const float*)d_in[0];
    const int*   ei     = (const int*)  d_in[1];
    const float* ew     = (const float*)d_in[2];
    const float* Ws     = (const float*)d_in[3];
    const float* bs     = (const float*)d_in[4];
    const float* gammas = (const float*)d_in[5];
    const float* betas  = (const float*)d_in[6];
    float* out = (float*)d_out;

    __half* xwh = nullptr; cudaGetSymbolAddress((void**)&xwh, g_xwh);
    float* hA = nullptr; cudaGetSymbolAddress((void**)&hA, g_hA);
    float* hB = nullptr; cudaGetSymbolAddress((void**)&hB, g_hB);
    __nv_bfloat16* xhi = nullptr; cudaGetSymbolAddress((void**)&xhi, g_xhi);
    __nv_bfloat16* xlo = nullptr; cudaGetSymbolAddress((void**)&xlo, g_xlo);
    __nv_bfloat16* Whi = nullptr; cudaGetSymbolAddress((void**)&Whi, g_Whi);
    __nv_bfloat16* Wlo = nullptr; cudaGetSymbolAddress((void**)&Wlo, g_Wlo);

    cudaFuncSetAttribute(k_mma, cudaFuncAttributeMaxDynamicSharedMemorySize, SMEM_MMA_TOTAL);

    int gE = (EE + 255) / 256;                 // 6250
    int gMain = 25192 + gE;                    // conv + W + degcnt blocks
    int gMma = (NN + 127) / 128;
    int gAgg = NN / 8;

    k_init<<<(NN + 255) / 256, 256>>>();
    k_main<<<gMain, 256>>>(x, Ws, ei, ew);
    k_scan1<<<SCAN_B, 1024>>>();
    k_scan3<<<SCAN_B, 1024>>>();
    k_fill<<<gE, 256>>>(ei, ew);

    k_mma<<<gMma, 256, SMEM_MMA_TOTAL>>>(xhi, xlo, Whi + 0 * DD * DD, Wlo + 0 * DD * DD, xwh);
    k_agg<<<gAgg, 256>>>(xwh, x, bs + 0 * DD, gammas + 0 * DD, betas + 0 * DD, hA, 1 | 2);
    k_mma<<<gMma, 256, SMEM_MMA_TOTAL>>>(xhi, xlo, Whi + 1 * DD * DD, Wlo + 1 * DD * DD, xwh);
    k_agg<<<gAgg, 256>>>(xwh, hA, bs + 1 * DD, gammas + 1 * DD, betas + 1 * DD, hB, 1 | 2);
    k_mma<<<gMma, 256, SMEM_MMA_TOTAL>>>(xhi, xlo, Whi + 2 * DD * DD, Wlo + 2 * DD * DD, xwh);
    k_agg<<<gAgg, 256>>>(xwh, hB, bs + 2 * DD, gammas + 2 * DD, betas + 2 * DD, out, 0);
}

// round 11
// speedup vs baseline: 3.0963x; 1.1458x over previous
#include <cuda_runtime.h>
#include <cuda_bf16.h>
#include <cuda_fp16.h>
#include <cstdint>

#define NN 50000
#define EE 1600000
#define DD 128
#define LN_EPS 1e-5f
#define SCAN_B 49   // ceil(NN / 1024)

// ---------------- scratch (static device globals) ---------------------------
__device__ float g_deg[NN];
__device__ float g_dinv[NN];
__device__ int   g_cnt[NN];
__device__ int   g_rowptr[NN + 1];
__device__ int   g_cursor[NN];
__device__ int   g_bsum[SCAN_B];
__device__ int2  g_edge[EE];                    // (src, norm bits)
__device__ __half g_xwh[(size_t)NN * DD];       // fp16 GEMM output (gather source)
__device__ __half g_xh[(size_t)NN * DD];        // fp16 GEMM input (current h)
__device__ __half g_Wh[3 * DD * DD];            // fp16 weights
__device__ float g_hA[(size_t)NN * DD];
__device__ float g_hB[(size_t)NN * DD];

__device__ __forceinline__ uint32_t smem_to_u32(const void* p) {
    uint32_t a;
    asm("{ .reg .u64 t; cvta.to.shared.u64 t, %1; cvt.u32.u64 %0, t; }" : "=r"(a) : "l"(p));
    return a;
}

// ---------------- merged conversion + degree/count kernel --------------------
// blocks [0,25000): x -> fp16 ; [25000,25192): W -> fp16 ; rest: degcnt
__global__ __launch_bounds__(256) void k_main(const float* __restrict__ x,
                                              const float* __restrict__ Ws,
                                              const int* __restrict__ ei,
                                              const float* __restrict__ ew) {
    int b = blockIdx.x, t = threadIdx.x;
    if (b < 25000) {
        int i = b * 256 + t;
        g_xh[i] = __float2half_rn(x[i]);
    } else if (b < 25192) {
        int j = (b - 25000) * 256 + t;     // < 49152
        g_Wh[j] = __float2half_rn(Ws[j]);
    } else {
        int e = (b - 25192) * 256 + t;
        if (e < EE) {
            int c = ei[EE + e];
            atomicAdd(&g_deg[c], ew[e]);
            atomicAdd(&g_cnt[c], 1);
        }
    }
}

// ---------------- hierarchical scan: 49 blocks x 1024 ------------------------
__global__ __launch_bounds__(1024) void k_scan1() {
    __shared__ int s_w[32];
    int b = blockIdx.x, t = threadIdx.x, lane = t & 31, wid = t >> 5;
    int i = b * 1024 + t;
    int v = (i < NN) ? g_cnt[i] : 0;
    int incl = v;
    #pragma unroll
    for (int off = 1; off < 32; off <<= 1) {
        int u = __shfl_up_sync(0xffffffffu, incl, off);
        if (lane >= off) incl += u;
    }
    if (lane == 31) s_w[wid] = incl;
    __syncthreads();
    if (wid == 0) {
        int w = s_w[lane];
        #pragma unroll
        for (int off = 1; off < 32; off <<= 1) {
            int u = __shfl_up_sync(0xffffffffu, w, off);
            if (lane >= off) w += u;
        }
        s_w[lane] = w;
    }
    __syncthreads();
    int base = (wid == 0) ? 0 : s_w[wid - 1];
    if (i < NN) g_rowptr[i] = base + incl - v;     // block-local exclusive
    if (t == 1023) g_bsum[b] = s_w[31];            // block total
}

// apply block offsets (each block reduces bsum itself), cursor, dinv (+self loop)
__global__ __launch_bounds__(1024) void k_scan3() {
    __shared__ int s_off;
    int b = blockIdx.x, t = threadIdx.x, lane = t & 31;
    if (t < 32) {
        int acc = 0;
        if (lane < b) acc = g_bsum[lane];
        if (lane + 32 < b) acc += g_bsum[lane + 32];
        #pragma unroll
        for (int off = 16; off >= 1; off >>= 1) acc += __shfl_xor_sync(0xffffffffu, acc, off);
        if (lane == 0) s_off = acc;
    }
    __syncthreads();
    int i = b * 1024 + t;
    if (i < NN) {
        int rp = g_rowptr[i] + s_off;
        g_rowptr[i] = rp;
        g_cursor[i] = rp;
        float dg = g_deg[i] + 1.0f;     // + self-loop weight (deg memset to 0)
        g_deg[i] = dg;
        g_dinv[i] = rsqrtf(dg);
        if (i == 0) g_rowptr[NN] = EE;
    }
}

__global__ void k_fill(const int* __restrict__ ei, const float* __restrict__ ew) {
    int e = blockIdx.x * blockDim.x + threadIdx.x;
    if (e < EE) {
        int r = ei[e];
        int c = ei[EE + e];
        float nrm = __ldg(&g_dinv[r]) * ew[e] * __ldg(&g_dinv[c]);
        int pos = atomicAdd(&g_cursor[c], 1);
        g_edge[pos] = make_int2(r, __float_as_int(nrm));
    }
}

// ---------------- mma.sync fp16 GEMM (single pass): outh = fp16(A @ W^T) ----
#define PADB 136
#define TILE_B (128 * PADB * 2)
#define SMEM_MMA_TOTAL (2 * TILE_B)

__device__ __forceinline__ void ldsm_x4(uint32_t* r, uint32_t addr) {
    asm volatile("ldmatrix.sync.aligned.m8n8.x4.shared.b16 {%0,%1,%2,%3}, [%4];"
                 : "=r"(r[0]), "=r"(r[1]), "=r"(r[2]), "=r"(r[3]) : "r"(addr));
}
__device__ __forceinline__ void mma_f16(float* c, const uint32_t* a, const uint32_t* b) {
    asm volatile("mma.sync.aligned.m16n8k16.row.col.f32.f16.f16.f32 "
                 "{%0,%1,%2,%3}, {%4,%5,%6,%7}, {%8,%9}, {%0,%1,%2,%3};"
                 : "+f"(c[0]), "+f"(c[1]), "+f"(c[2]), "+f"(c[3])
                 : "r"(a[0]), "r"(a[1]), "r"(a[2]), "r"(a[3]), "r"(b[0]), "r"(b[1]));
}

__global__ __launch_bounds__(256) void k_mma(const __half* __restrict__ Ah,
                                             const __half* __restrict__ Wh,
                                             __half* __restrict__ outh) {
    extern __shared__ char smem[];
    uint32_t sbase = smem_to_u32(smem);
    int tid = threadIdx.x;
    int bm = blockIdx.x * 128;

    // load 2 tiles (A, W), each 128x128 fp16, padded rows
    #pragma unroll
    for (int it = 0; it < 16; it++) {
        int idx = tid + it * 256;            // 0..4095
        int tile = idx >> 11;
        int g = idx & 2047;
        int r = g >> 4, c8 = g & 15;
        uint32_t dst = (uint32_t)tile * TILE_B + ((uint32_t)r * PADB + (uint32_t)c8 * 8) * 2;
        uint4 v = make_uint4(0, 0, 0, 0);
        if (tile == 0) {
            int gr = bm + r;
            if (gr < NN) v = *(const uint4*)(Ah + (size_t)gr * 128 + c8 * 8);
        } else {
            v = *(const uint4*)(Wh + r * 128 + c8 * 8);
        }
        *(uint4*)(smem + dst) = v;
    }
    __syncthreads();

    int lane = tid & 31, warp = tid >> 5;
    int wm = warp >> 1, wn = warp & 1;

    uint32_t aoff[2];
    #pragma unroll
    for (int mi = 0; mi < 2; mi++) {
        int row = wm * 32 + mi * 16 + (lane & 15);
        aoff[mi] = ((uint32_t)row * PADB + (uint32_t)(lane >> 4) * 8) * 2;
    }
    uint32_t boff[4];
    #pragma unroll
    for (int pi = 0; pi < 4; pi++) {
        int row = wn * 64 + pi * 16 + (lane & 7) + 8 * ((lane >> 4) & 1);
        boff[pi] = ((uint32_t)row * PADB + (uint32_t)((lane >> 3) & 1) * 8) * 2;
    }

    uint32_t sA = sbase, sW = sbase + TILE_B;

    float C[2][8][4];
    #pragma unroll
    for (int mi = 0; mi < 2; mi++)
        #pragma unroll
        for (int ni = 0; ni < 8; ni++)
            #pragma unroll
            for (int q = 0; q < 4; q++) C[mi][ni][q] = 0.0f;

    #pragma unroll
    for (int ks = 0; ks < 8; ks++) {
        uint32_t kadv = (uint32_t)ks * 32;
        uint32_t a[2][4], bw[4][4];
        #pragma unroll
        for (int mi = 0; mi < 2; mi++) ldsm_x4(a[mi], sA + aoff[mi] + kadv);
        #pragma unroll
        for (int pi = 0; pi < 4; pi++) ldsm_x4(bw[pi], sW + boff[pi] + kadv);
        #pragma unroll
        for (int mi = 0; mi < 2; mi++) {
            #pragma unroll
            for (int ni = 0; ni < 8; ni++) {
                mma_f16(C[mi][ni], a[mi], &bw[ni >> 1][(ni & 1) * 2]);
            }
        }
    }

    // epilogue: fp16 stores
    int g = lane >> 2, ctg = lane & 3;
    #pragma unroll
    for (int mi = 0; mi < 2; mi++) {
        int r0 = bm + wm * 32 + mi * 16 + g;
        #pragma unroll
        for (int ni = 0; ni < 8; ni++) {
            int col = wn * 64 + ni * 8 + ctg * 2;
            if (r0 < NN)
                *(__half2*)&outh[(size_t)r0 * 128 + col] =
                    __floats2half2_rn(C[mi][ni][0], C[mi][ni][1]);
            if (r0 + 8 < NN)
                *(__half2*)&outh[(size_t)(r0 + 8) * 128 + col] =
                    __floats2half2_rn(C[mi][ni][2], C[mi][ni][3]);
        }
    }
}

// ---------------- warp-per-node aggregate + LN + ReLU + residual ------------
__global__ __launch_bounds__(256) void k_agg(const __half* __restrict__ xwh,
                                             const float* __restrict__ hin,
                                             const float* __restrict__ bias,
                                             const float* __restrict__ gamma,
                                             const float* __restrict__ beta,
                                             float* __restrict__ hout,
                                             int flags) {   // bit0 relu, bit1 conv
    int warp = threadIdx.x >> 5, lane = threadIdx.x & 31;
    int n = blockIdx.x * 8 + warp;     // grid 6250 * 8 = 50000 exact
    int d0 = lane * 4;

    float invdeg = 1.0f / __ldg(&g_deg[n]);
    uint2 sv = __ldg((const uint2*)(xwh + (size_t)n * DD + d0));
    float2 s01 = __half22float2(*(const __half2*)&sv.x);
    float2 s23 = __half22float2(*(const __half2*)&sv.y);
    float4 bv = __ldg((const float4*)&bias[d0]);
    float a0 = invdeg * s01.x + bv.x;
    float a1 = invdeg * s01.y + bv.y;
    float a2 = invdeg * s23.x + bv.z;
    float a3 = invdeg * s23.y + bv.w;

    int beg = __ldg(&g_rowptr[n]), end = __ldg(&g_rowptr[n + 1]);
    int j = beg;
    for (; j + 7 < end; j += 8) {
        int2 e0 = __ldg(&g_edge[j]);
        int2 e1 = __ldg(&g_edge[j + 1]);
        int2 e2 = __ldg(&g_edge[j + 2]);
        int2 e3 = __ldg(&g_edge[j + 3]);
        int2 e4 = __ldg(&g_edge[j + 4]);
        int2 e5 = __ldg(&g_edge[j + 5]);
        int2 e6 = __ldg(&g_edge[j + 6]);
        int2 e7 = __ldg(&g_edge[j + 7]);
        uint2 v0 = __ldg((const uint2*)(xwh + (size_t)e0.x * DD + d0));
        uint2 v1 = __ldg((const uint2*)(xwh + (size_t)e1.x * DD + d0));
        uint2 v2 = __ldg((const uint2*)(xwh + (size_t)e2.x * DD + d0));
        uint2 v3 = __ldg((const uint2*)(xwh + (size_t)e3.x * DD + d0));
        uint2 v4 = __ldg((const uint2*)(xwh + (size_t)e4.x * DD + d0));
        uint2 v5 = __ldg((const uint2*)(xwh + (size_t)e5.x * DD + d0));
        uint2 v6 = __ldg((const uint2*)(xwh + (size_t)e6.x * DD + d0));
        uint2 v7 = __ldg((const uint2*)(xwh + (size_t)e7.x * DD + d0));
        float w0 = __int_as_float(e0.y), w1 = __int_as_float(e1.y);
        float w2 = __int_as_float(e2.y), w3 = __int_as_float(e3.y);
        float w4 = __int_as_float(e4.y), w5 = __int_as_float(e5.y);
        float w6 = __int_as_float(e6.y), w7 = __int_as_float(e7.y);
        float2 p, q;
        p = __half22float2(*(const __half2*)&v0.x); q = __half22float2(*(const __half2*)&v0.y);
        a0 += w0 * p.x; a1 += w0 * p.y; a2 += w0 * q.x; a3 += w0 * q.y;
        p = __half22float2(*(const __half2*)&v1.x); q = __half22float2(*(const __half2*)&v1.y);
        a0 += w1 * p.x; a1 += w1 * p.y; a2 += w1 * q.x; a3 += w1 * q.y;
        p = __half22float2(*(const __half2*)&v2.x); q = __half22float2(*(const __half2*)&v2.y);
        a0 += w2 * p.x; a1 += w2 * p.y; a2 += w2 * q.x; a3 += w2 * q.y;
        p = __half22float2(*(const __half2*)&v3.x); q = __half22float2(*(const __half2*)&v3.y);
        a0 += w3 * p.x; a1 += w3 * p.y; a2 += w3 * q.x; a3 += w3 * q.y;
        p = __half22float2(*(const __half2*)&v4.x); q = __half22float2(*(const __half2*)&v4.y);
        a0 += w4 * p.x; a1 += w4 * p.y; a2 += w4 * q.x; a3 += w4 * q.y;
        p = __half22float2(*(const __half2*)&v5.x); q = __half22float2(*(const __half2*)&v5.y);
        a0 += w5 * p.x; a1 += w5 * p.y; a2 += w5 * q.x; a3 += w5 * q.y;
        p = __half22float2(*(const __half2*)&v6.x); q = __half22float2(*(const __half2*)&v6.y);
        a0 += w6 * p.x; a1 += w6 * p.y; a2 += w6 * q.x; a3 += w6 * q.y;
        p = __half22float2(*(const __half2*)&v7.x); q = __half22float2(*(const __half2*)&v7.y);
        a0 += w7 * p.x; a1 += w7 * p.y; a2 += w7 * q.x; a3 += w7 * q.y;
    }
    for (; j < end; j++) {
        int2 e = __ldg(&g_edge[j]);
        float w = __int_as_float(e.y);
        uint2 v = __ldg((const uint2*)(xwh + (size_t)e.x * DD + d0));
        float2 p = __half22float2(*(const __half2*)&v.x);
        float2 q = __half22float2(*(const __half2*)&v.y);
        a0 += w * p.x; a1 += w * p.y; a2 += w * q.x; a3 += w * q.y;
    }

    // warp-level LayerNorm over 128 features (4 per lane)
    float s = a0 + a1 + a2 + a3;
    #pragma unroll
    for (int off = 16; off >= 1; off >>= 1) s += __shfl_xor_sync(0xffffffffu, s, off);
    float mu = s * (1.0f / 128.0f);

    float d0f = a0 - mu, d1f = a1 - mu, d2f = a2 - mu, d3f = a3 - mu;
    float q = d0f * d0f + d1f * d1f + d2f * d2f + d3f * d3f;
    #pragma unroll
    for (int off = 16; off >= 1; off >>= 1) q += __shfl_xor_sync(0xffffffffu, q, off);
    float rstd = rsqrtf(q * (1.0f / 128.0f) + LN_EPS);

    float4 gv = __ldg((const float4*)&gamma[d0]);
    float4 bt = __ldg((const float4*)&beta[d0]);
    float y0 = d0f * rstd * gv.x + bt.x;
    float y1 = d1f * rstd * gv.y + bt.y;
    float y2 = d2f * rstd * gv.z + bt.z;
    float y3 = d3f * rstd * gv.w + bt.w;
    if (flags & 1) {
        y0 = fmaxf(y0, 0.0f); y1 = fmaxf(y1, 0.0f);
        y2 = fmaxf(y2, 0.0f); y3 = fmaxf(y3, 0.0f);
    }
    float4 hv = __ldg((const float4*)&hin[(size_t)n * DD + d0]);
    y0 += hv.x; y1 += hv.y; y2 += hv.z; y3 += hv.w;
    *(float4*)&hout[(size_t)n * DD + d0] = make_float4(y0, y1, y2, y3);

    if (flags & 2) {
        size_t i = (size_t)n * DD + d0;
        __half2 h01 = __floats2half2_rn(y0, y1);
        __half2 h23 = __floats2half2_rn(y2, y3);
        *(uint2*)&g_xh[i] = make_uint2(*(uint32_t*)&h01, *(uint32_t*)&h23);
    }
}

// ---------------- launch ----------------------------------------------------
extern "C" void kernel_launch(void* const* d_in, const int* in_sizes, int n_in,
                              void* d_out, int out_size) {
    const float* x      = (const float*)d_in[0];
    const int*   ei     = (const int*)  d_in[1];
    const float* ew     = (const float*)d_in[2];
    const float* Ws     = (const float*)d_in[3];
    const float* bs     = (const float*)d_in[4];
    const float* gammas = (const float*)d_in[5];
    const float* betas  = (const float*)d_in[6];
    float* out = (float*)d_out;

    __half* xwh = nullptr; cudaGetSymbolAddress((void**)&xwh, g_xwh);
    __half* xh  = nullptr; cudaGetSymbolAddress((void**)&xh, g_xh);
    __half* Wh  = nullptr; cudaGetSymbolAddress((void**)&Wh, g_Wh);
    float* hA = nullptr; cudaGetSymbolAddress((void**)&hA, g_hA);
    float* hB = nullptr; cudaGetSymbolAddress((void**)&hB, g_hB);
    float* degp = nullptr; cudaGetSymbolAddress((void**)&degp, g_deg);
    int*   cntp = nullptr; cudaGetSymbolAddress((void**)&cntp, g_cnt);

    cudaFuncSetAttribute(k_mma, cudaFuncAttributeMaxDynamicSharedMemorySize, SMEM_MMA_TOTAL);

    int gE = (EE + 255) / 256;                 // 6250
    int gMain = 25192 + gE;                    // conv + W + degcnt blocks
    int gMma = (NN + 127) / 128;
    int gAgg = NN / 8;

    cudaMemsetAsync(degp, 0, NN * sizeof(float));
    cudaMemsetAsync(cntp, 0, NN * sizeof(int));
    k_main<<<gMain, 256>>>(x, Ws, ei, ew);
    k_scan1<<<SCAN_B, 1024>>>();
    k_scan3<<<SCAN_B, 1024>>>();
    k_fill<<<gE, 256>>>(ei, ew);

    k_mma<<<gMma, 256, SMEM_MMA_TOTAL>>>(xh, Wh + 0 * DD * DD, xwh);
    k_agg<<<gAgg, 256>>>(xwh, x, bs + 0 * DD, gammas + 0 * DD, betas + 0 * DD, hA, 1 | 2);
    k_mma<<<gMma, 256, SMEM_MMA_TOTAL>>>(xh, Wh + 1 * DD * DD, xwh);
    k_agg<<<gAgg, 256>>>(xwh, hA, bs + 1 * DD, gammas + 1 * DD, betas + 1 * DD, hB, 1 | 2);
    k_mma<<<gMma, 256, SMEM_MMA_TOTAL>>>(xh, Wh + 2 * DD * DD, xwh);
    k_agg<<<gAgg, 256>>>(xwh, hB, bs + 2 * DD, gammas + 2 * DD, betas + 2 * DD, out, 0);
}

// round 12
// speedup vs baseline: 3.2780x; 1.0587x over previous
#include <cuda_runtime.h>
#include <cuda_bf16.h>
#include <cuda_fp16.h>
#include <cstdint>

#define NN 50000
#define EE 1600000
#define DD 128
#define LN_EPS 1e-5f
#define SCAN_B 49   // ceil(NN / 1024)

// ---------------- scratch (static device globals) ---------------------------
__device__ float g_deg[NN];
__device__ float g_dinv[NN];
__device__ int   g_cnt[NN];
__device__ int   g_rowptr[NN + 1];
__device__ int   g_cursor[NN];
__device__ int   g_bsum[SCAN_B];
__device__ int2  g_edge[EE];                    // (src, norm bits)
__device__ __half g_xwh[(size_t)NN * DD];       // fp16 GEMM output (gather source)
__device__ __half g_xh[(size_t)NN * DD];        // fp16 current h (GEMM input + residual)
__device__ __half g_Wh[3 * DD * DD];            // fp16 weights

__device__ __forceinline__ uint32_t smem_to_u32(const void* p) {
    uint32_t a;
    asm("{ .reg .u64 t; cvta.to.shared.u64 t, %1; cvt.u32.u64 %0, t; }" : "=r"(a) : "l"(p));
    return a;
}

// ---------------- merged conversion + degree/count kernel --------------------
__global__ __launch_bounds__(256) void k_main(const float* __restrict__ x,
                                              const float* __restrict__ Ws,
                                              const int* __restrict__ ei,
                                              const float* __restrict__ ew) {
    int b = blockIdx.x, t = threadIdx.x;
    if (b < 25000) {
        int i = b * 256 + t;
        g_xh[i] = __float2half_rn(x[i]);
    } else if (b < 25192) {
        int j = (b - 25000) * 256 + t;     // < 49152
        g_Wh[j] = __float2half_rn(Ws[j]);
    } else {
        int e = (b - 25192) * 256 + t;
        if (e < EE) {
            int c = ei[EE + e];
            atomicAdd(&g_deg[c], ew[e]);
            atomicAdd(&g_cnt[c], 1);
        }
    }
}

// ---------------- hierarchical scan: 49 blocks x 1024 ------------------------
__global__ __launch_bounds__(1024) void k_scan1() {
    __shared__ int s_w[32];
    int b = blockIdx.x, t = threadIdx.x, lane = t & 31, wid = t >> 5;
    int i = b * 1024 + t;
    int v = (i < NN) ? g_cnt[i] : 0;
    int incl = v;
    #pragma unroll
    for (int off = 1; off < 32; off <<= 1) {
        int u = __shfl_up_sync(0xffffffffu, incl, off);
        if (lane >= off) incl += u;
    }
    if (lane == 31) s_w[wid] = incl;
    __syncthreads();
    if (wid == 0) {
        int w = s_w[lane];
        #pragma unroll
        for (int off = 1; off < 32; off <<= 1) {
            int u = __shfl_up_sync(0xffffffffu, w, off);
            if (lane >= off) w += u;
        }
        s_w[lane] = w;
    }
    __syncthreads();
    int base = (wid == 0) ? 0 : s_w[wid - 1];
    if (i < NN) g_rowptr[i] = base + incl - v;
    if (t == 1023) g_bsum[b] = s_w[31];
}

// apply block offsets, cursor, dinv (+self loop)
__global__ __launch_bounds__(1024) void k_scan3() {
    __shared__ int s_off;
    int b = blockIdx.x, t = threadIdx.x, lane = t & 31;
    if (t < 32) {
        int acc = 0;
        if (lane < b) acc = g_bsum[lane];
        if (lane + 32 < b) acc += g_bsum[lane + 32];
        #pragma unroll
        for (int off = 16; off >= 1; off >>= 1) acc += __shfl_xor_sync(0xffffffffu, acc, off);
        if (lane == 0) s_off = acc;
    }
    __syncthreads();
    int i = b * 1024 + t;
    if (i < NN) {
        int rp = g_rowptr[i] + s_off;
        g_rowptr[i] = rp;
        g_cursor[i] = rp;
        float dg = g_deg[i] + 1.0f;     // self-loop (deg memset to 0)
        g_deg[i] = dg;
        g_dinv[i] = rsqrtf(dg);
        if (i == 0) g_rowptr[NN] = EE;
    }
}

__global__ void k_fill(const int* __restrict__ ei, const float* __restrict__ ew) {
    int e = blockIdx.x * blockDim.x + threadIdx.x;
    if (e < EE) {
        int r = ei[e];
        int c = ei[EE + e];
        float nrm = __ldg(&g_dinv[r]) * ew[e] * __ldg(&g_dinv[c]);
        int pos = atomicAdd(&g_cursor[c], 1);
        g_edge[pos] = make_int2(r, __float_as_int(nrm));
    }
}

// ---------------- mma.sync fp16 GEMM (single pass): outh = fp16(A @ W^T) ----
#define PADB 136
#define TILE_B (128 * PADB * 2)
#define SMEM_MMA_TOTAL (2 * TILE_B)

__device__ __forceinline__ void ldsm_x4(uint32_t* r, uint32_t addr) {
    asm volatile("ldmatrix.sync.aligned.m8n8.x4.shared.b16 {%0,%1,%2,%3}, [%4];"
                 : "=r"(r[0]), "=r"(r[1]), "=r"(r[2]), "=r"(r[3]) : "r"(addr));
}
__device__ __forceinline__ void mma_f16(float* c, const uint32_t* a, const uint32_t* b) {
    asm volatile("mma.sync.aligned.m16n8k16.row.col.f32.f16.f16.f32 "
                 "{%0,%1,%2,%3}, {%4,%5,%6,%7}, {%8,%9}, {%0,%1,%2,%3};"
                 : "+f"(c[0]), "+f"(c[1]), "+f"(c[2]), "+f"(c[3])
                 : "r"(a[0]), "r"(a[1]), "r"(a[2]), "r"(a[3]), "r"(b[0]), "r"(b[1]));
}

__global__ __launch_bounds__(256) void k_mma(const __half* __restrict__ Ah,
                                             const __half* __restrict__ Wh,
                                             __half* __restrict__ outh) {
    extern __shared__ char smem[];
    uint32_t sbase = smem_to_u32(smem);
    int tid = threadIdx.x;
    int bm = blockIdx.x * 128;

    #pragma unroll
    for (int it = 0; it < 16; it++) {
        int idx = tid + it * 256;            // 0..4095
        int tile = idx >> 11;
        int g = idx & 2047;
        int r = g >> 4, c8 = g & 15;
        uint32_t dst = (uint32_t)tile * TILE_B + ((uint32_t)r * PADB + (uint32_t)c8 * 8) * 2;
        uint4 v = make_uint4(0, 0, 0, 0);
        if (tile == 0) {
            int gr = bm + r;
            if (gr < NN) v = *(const uint4*)(Ah + (size_t)gr * 128 + c8 * 8);
        } else {
            v = *(const uint4*)(Wh + r * 128 + c8 * 8);
        }
        *(uint4*)(smem + dst) = v;
    }
    __syncthreads();

    int lane = tid & 31, warp = tid >> 5;
    int wm = warp >> 1, wn = warp & 1;

    uint32_t aoff[2];
    #pragma unroll
    for (int mi = 0; mi < 2; mi++) {
        int row = wm * 32 + mi * 16 + (lane & 15);
        aoff[mi] = ((uint32_t)row * PADB + (uint32_t)(lane >> 4) * 8) * 2;
    }
    uint32_t boff[4];
    #pragma unroll
    for (int pi = 0; pi < 4; pi++) {
        int row = wn * 64 + pi * 16 + (lane & 7) + 8 * ((lane >> 4) & 1);
        boff[pi] = ((uint32_t)row * PADB + (uint32_t)((lane >> 3) & 1) * 8) * 2;
    }

    uint32_t sA = sbase, sW = sbase + TILE_B;

    float C[2][8][4];
    #pragma unroll
    for (int mi = 0; mi < 2; mi++)
        #pragma unroll
        for (int ni = 0; ni < 8; ni++)
            #pragma unroll
            for (int q = 0; q < 4; q++) C[mi][ni][q] = 0.0f;

    #pragma unroll
    for (int ks = 0; ks < 8; ks++) {
        uint32_t kadv = (uint32_t)ks * 32;
        uint32_t a[2][4], bw[4][4];
        #pragma unroll
        for (int mi = 0; mi < 2; mi++) ldsm_x4(a[mi], sA + aoff[mi] + kadv);
        #pragma unroll
        for (int pi = 0; pi < 4; pi++) ldsm_x4(bw[pi], sW + boff[pi] + kadv);
        #pragma unroll
        for (int mi = 0; mi < 2; mi++) {
            #pragma unroll
            for (int ni = 0; ni < 8; ni++) {
                mma_f16(C[mi][ni], a[mi], &bw[ni >> 1][(ni & 1) * 2]);
            }
        }
    }

    int g = lane >> 2, ctg = lane & 3;
    #pragma unroll
    for (int mi = 0; mi < 2; mi++) {
        int r0 = bm + wm * 32 + mi * 16 + g;
        #pragma unroll
        for (int ni = 0; ni < 8; ni++) {
            int col = wn * 64 + ni * 8 + ctg * 2;
            if (r0 < NN)
                *(__half2*)&outh[(size_t)r0 * 128 + col] =
                    __floats2half2_rn(C[mi][ni][0], C[mi][ni][1]);
            if (r0 + 8 < NN)
                *(__half2*)&outh[(size_t)(r0 + 8) * 128 + col] =
                    __floats2half2_rn(C[mi][ni][2], C[mi][ni][3]);
        }
    }
}

// ---------------- warp-per-node aggregate + LN + ReLU + residual ------------
// flags: bit0 relu, bit1 residual from fp32 hinf, bit2 write fp32 hout,
//        bit3 write fp16 xh (next-layer input)
__global__ __launch_bounds__(256) void k_agg(const __half* __restrict__ xwh,
                                             const float* __restrict__ hinf,
                                             __half* __restrict__ xh_io,
                                             const float* __restrict__ bias,
                                             const float* __restrict__ gamma,
                                             const float* __restrict__ beta,
                                             float* __restrict__ hout,
                                             int flags) {
    int warp = threadIdx.x >> 5, lane = threadIdx.x & 31;
    int n = blockIdx.x * 8 + warp;     // grid 6250 * 8 = 50000 exact
    int d0 = lane * 4;

    float invdeg = 1.0f / __ldg(&g_deg[n]);
    uint2 sv = __ldg((const uint2*)(xwh + (size_t)n * DD + d0));
    float2 s01 = __half22float2(*(const __half2*)&sv.x);
    float2 s23 = __half22float2(*(const __half2*)&sv.y);
    float4 bv = __ldg((const float4*)&bias[d0]);
    float a0 = invdeg * s01.x + bv.x;
    float a1 = invdeg * s01.y + bv.y;
    float a2 = invdeg * s23.x + bv.z;
    float a3 = invdeg * s23.y + bv.w;

    int beg = __ldg(&g_rowptr[n]), end = __ldg(&g_rowptr[n + 1]);
    int j = beg;
    for (; j + 7 < end; j += 8) {
        int2 e0 = __ldg(&g_edge[j]);
        int2 e1 = __ldg(&g_edge[j + 1]);
        int2 e2 = __ldg(&g_edge[j + 2]);
        int2 e3 = __ldg(&g_edge[j + 3]);
        int2 e4 = __ldg(&g_edge[j + 4]);
        int2 e5 = __ldg(&g_edge[j + 5]);
        int2 e6 = __ldg(&g_edge[j + 6]);
        int2 e7 = __ldg(&g_edge[j + 7]);
        uint2 v0 = __ldg((const uint2*)(xwh + (size_t)e0.x * DD + d0));
        uint2 v1 = __ldg((const uint2*)(xwh + (size_t)e1.x * DD + d0));
        uint2 v2 = __ldg((const uint2*)(xwh + (size_t)e2.x * DD + d0));
        uint2 v3 = __ldg((const uint2*)(xwh + (size_t)e3.x * DD + d0));
        uint2 v4 = __ldg((const uint2*)(xwh + (size_t)e4.x * DD + d0));
        uint2 v5 = __ldg((const uint2*)(xwh + (size_t)e5.x * DD + d0));
        uint2 v6 = __ldg((const uint2*)(xwh + (size_t)e6.x * DD + d0));
        uint2 v7 = __ldg((const uint2*)(xwh + (size_t)e7.x * DD + d0));
        float w0 = __int_as_float(e0.y), w1 = __int_as_float(e1.y);
        float w2 = __int_as_float(e2.y), w3 = __int_as_float(e3.y);
        float w4 = __int_as_float(e4.y), w5 = __int_as_float(e5.y);
        float w6 = __int_as_float(e6.y), w7 = __int_as_float(e7.y);
        float2 p, q;
        p = __half22float2(*(const __half2*)&v0.x); q = __half22float2(*(const __half2*)&v0.y);
        a0 += w0 * p.x; a1 += w0 * p.y; a2 += w0 * q.x; a3 += w0 * q.y;
        p = __half22float2(*(const __half2*)&v1.x); q = __half22float2(*(const __half2*)&v1.y);
        a0 += w1 * p.x; a1 += w1 * p.y; a2 += w1 * q.x; a3 += w1 * q.y;
        p = __half22float2(*(const __half2*)&v2.x); q = __half22float2(*(const __half2*)&v2.y);
        a0 += w2 * p.x; a1 += w2 * p.y; a2 += w2 * q.x; a3 += w2 * q.y;
        p = __half22float2(*(const __half2*)&v3.x); q = __half22float2(*(const __half2*)&v3.y);
        a0 += w3 * p.x; a1 += w3 * p.y; a2 += w3 * q.x; a3 += w3 * q.y;
        p = __half22float2(*(const __half2*)&v4.x); q = __half22float2(*(const __half2*)&v4.y);
        a0 += w4 * p.x; a1 += w4 * p.y; a2 += w4 * q.x; a3 += w4 * q.y;
        p = __half22float2(*(const __half2*)&v5.x); q = __half22float2(*(const __half2*)&v5.y);
        a0 += w5 * p.x; a1 += w5 * p.y; a2 += w5 * q.x; a3 += w5 * q.y;
        p = __half22float2(*(const __half2*)&v6.x); q = __half22float2(*(const __half2*)&v6.y);
        a0 += w6 * p.x; a1 += w6 * p.y; a2 += w6 * q.x; a3 += w6 * q.y;
        p = __half22float2(*(const __half2*)&v7.x); q = __half22float2(*(const __half2*)&v7.y);
        a0 += w7 * p.x; a1 += w7 * p.y; a2 += w7 * q.x; a3 += w7 * q.y;
    }
    for (; j < end; j++) {
        int2 e = __ldg(&g_edge[j]);
        float w = __int_as_float(e.y);
        uint2 v = __ldg((const uint2*)(xwh + (size_t)e.x * DD + d0));
        float2 p = __half22float2(*(const __half2*)&v.x);
        float2 q = __half22float2(*(const __half2*)&v.y);
        a0 += w * p.x; a1 += w * p.y; a2 += w * q.x; a3 += w * q.y;
    }

    // warp-level LayerNorm over 128 features (4 per lane)
    float s = a0 + a1 + a2 + a3;
    #pragma unroll
    for (int off = 16; off >= 1; off >>= 1) s += __shfl_xor_sync(0xffffffffu, s, off);
    float mu = s * (1.0f / 128.0f);

    float d0f = a0 - mu, d1f = a1 - mu, d2f = a2 - mu, d3f = a3 - mu;
    float q = d0f * d0f + d1f * d1f + d2f * d2f + d3f * d3f;
    #pragma unroll
    for (int off = 16; off >= 1; off >>= 1) q += __shfl_xor_sync(0xffffffffu, q, off);
    float rstd = rsqrtf(q * (1.0f / 128.0f) + LN_EPS);

    float4 gv = __ldg((const float4*)&gamma[d0]);
    float4 bt = __ldg((const float4*)&beta[d0]);
    float y0 = d0f * rstd * gv.x + bt.x;
    float y1 = d1f * rstd * gv.y + bt.y;
    float y2 = d2f * rstd * gv.z + bt.z;
    float y3 = d3f * rstd * gv.w + bt.w;
    if (flags & 1) {
        y0 = fmaxf(y0, 0.0f); y1 = fmaxf(y1, 0.0f);
        y2 = fmaxf(y2, 0.0f); y3 = fmaxf(y3, 0.0f);
    }

    // residual
    if (flags & 2) {
        float4 hv = __ldg((const float4*)&hinf[(size_t)n * DD + d0]);
        y0 += hv.x; y1 += hv.y; y2 += hv.z; y3 += hv.w;
    } else {
        uint2 hv = __ldg((const uint2*)(xh_io + (size_t)n * DD + d0));
        float2 h01 = __half22float2(*(const __half2*)&hv.x);
        float2 h23 = __half22float2(*(const __half2*)&hv.y);
        y0 += h01.x; y1 += h01.y; y2 += h23.x; y3 += h23.y;
    }

    if (flags & 4)
        *(float4*)&hout[(size_t)n * DD + d0] = make_float4(y0, y1, y2, y3);
    if (flags & 8) {
        size_t i = (size_t)n * DD + d0;
        __half2 h01 = __floats2half2_rn(y0, y1);
        __half2 h23 = __floats2half2_rn(y2, y3);
        *(uint2*)&xh_io[i] = make_uint2(*(uint32_t*)&h01, *(uint32_t*)&h23);
    }
}

// ---------------- launch ----------------------------------------------------
extern "C" void kernel_launch(void* const* d_in, const int* in_sizes, int n_in,
                              void* d_out, int out_size) {
    const float* x      = (const float*)d_in[0];
    const int*   ei     = (const int*)  d_in[1];
    const float* ew     = (const float*)d_in[2];
    const float* Ws     = (const float*)d_in[3];
    const float* bs     = (const float*)d_in[4];
    const float* gammas = (const float*)d_in[5];
    const float* betas  = (const float*)d_in[6];
    float* out = (float*)d_out;

    __half* xwh = nullptr; cudaGetSymbolAddress((void**)&xwh, g_xwh);
    __half* xh  = nullptr; cudaGetSymbolAddress((void**)&xh, g_xh);
    __half* Wh  = nullptr; cudaGetSymbolAddress((void**)&Wh, g_Wh);
    float* degp = nullptr; cudaGetSymbolAddress((void**)&degp, g_deg);
    int*   cntp = nullptr; cudaGetSymbolAddress((void**)&cntp, g_cnt);

    cudaFuncSetAttribute(k_mma, cudaFuncAttributeMaxDynamicSharedMemorySize, SMEM_MMA_TOTAL);

    static cudaStream_t s2 = nullptr;
    static cudaEvent_t evFork = nullptr, evJoin = nullptr;
    if (!s2) {
        cudaStreamCreateWithFlags(&s2, cudaStreamNonBlocking);
        cudaEventCreateWithFlags(&evFork, cudaEventDisableTiming);
        cudaEventCreateWithFlags(&evJoin, cudaEventDisableTiming);
    }

    int gE = (EE + 255) / 256;                 // 6250
    int gMain = 25192 + gE;
    int gMma = (NN + 127) / 128;
    int gAgg = NN / 8;

    cudaMemsetAsync(degp, 0, NN * sizeof(float));
    cudaMemsetAsync(cntp, 0, NN * sizeof(int));
    k_main<<<gMain, 256>>>(x, Ws, ei, ew);

    // fork: layer-0 GEMM only needs xh/Wh — overlap with graph build
    cudaEventRecord(evFork, 0);
    cudaStreamWaitEvent(s2, evFork, 0);
    k_mma<<<gMma, 256, SMEM_MMA_TOTAL, s2>>>(xh, Wh + 0 * DD * DD, xwh);
    cudaEventRecord(evJoin, s2);

    k_scan1<<<SCAN_B, 1024>>>();
    k_scan3<<<SCAN_B, 1024>>>();
    k_fill<<<gE, 256>>>(ei, ew);
    cudaStreamWaitEvent(0, evJoin, 0);

    // layer 0: residual from fp32 x; write fp16 xh only
    k_agg<<<gAgg, 256>>>(xwh, x, xh, bs + 0 * DD, gammas + 0 * DD, betas + 0 * DD, out, 1 | 2 | 8);
    // layer 1: residual fp16 xh; write fp16 xh
    k_mma<<<gMma, 256, SMEM_MMA_TOTAL>>>(xh, Wh + 1 * DD * DD, xwh);
    k_agg<<<gAgg, 256>>>(xwh, x, xh, bs + 1 * DD, gammas + 1 * DD, betas + 1 * DD, out, 1 | 8);
    // layer 2: residual fp16 xh; write fp32 out
    k_mma<<<gMma, 256, SMEM_MMA_TOTAL>>>(xh, Wh + 2 * DD * DD, xwh);
    k_agg<<<gAgg, 256>>>(xwh, x, xh, bs + 2 * DD, gammas + 2 * DD, betas + 2 * DD, out, 4);
}